// round 1
// baseline (speedup 1.0000x reference)
#include <cuda_runtime.h>
#include <math.h>

#define S 2048
#define DIM 2048
#define NH 16
#define NKV 8
#define HD 128
#define HID 5632
#define QKV_DIM ((NH + 2*NKV) * HD)   // 4096
#define EPS 1e-5f

// ---------------- scratch (static device globals; no runtime allocation) ----------------
__device__ float g_h[(size_t)S * DIM];                 // rmsnorm output (reused for ffn norm)
__device__ float g_qkv[(size_t)S * QKV_DIM];           // fused qkv (q|k|v per row)
__device__ float g_scores[(size_t)NH * S * S];         // attention scores / probs
__device__ float g_o[(size_t)S * DIM];                 // attention context (heads concatenated)
__device__ float g_tmp[(size_t)S * DIM];               // attn proj out / ffn out
__device__ float g_h2[(size_t)S * DIM];                // residual 1
__device__ float g_x13[(size_t)S * 2 * HID];           // w13 output
__device__ float g_gate[(size_t)S * HID];              // silu(x1)*x3

// ---------------- generic tiled GEMMs ----------------
// C[M,N] = A[M,K] @ B[N,K]^T   (row-major, arbitrary leading dims, batched via blockIdx.z)
#define BM 64
#define BN 64
#define BK 16

__global__ void gemm_nt(const float* __restrict__ A, const float* __restrict__ B,
                        float* __restrict__ C,
                        int M, int N, int K, int lda, int ldb, int ldc,
                        long long aBOff, long long bBOff, int bDiv, long long cBOff)
{
    int z = blockIdx.z;
    A += (long long)z * aBOff;
    B += (long long)(z / bDiv) * bBOff;
    C += (long long)z * cBOff;

    __shared__ float As[BK][BM + 4];
    __shared__ float Bs[BK][BN + 4];

    int tid = threadIdx.x;            // 256 threads
    int bm = blockIdx.y * BM;
    int bn = blockIdx.x * BN;
    int tx = tid & 15;                // 0..15
    int ty = tid >> 4;                // 0..15

    int lr = tid >> 2;                // 0..63 : row within tile
    int lc = (tid & 3) * 4;           // 0,4,8,12 : k-chunk within tile

    float acc[4][4] = {};

    for (int k0 = 0; k0 < K; k0 += BK) {
        float4 a4 = *reinterpret_cast<const float4*>(&A[(long long)(bm + lr) * lda + k0 + lc]);
        As[lc + 0][lr] = a4.x; As[lc + 1][lr] = a4.y;
        As[lc + 2][lr] = a4.z; As[lc + 3][lr] = a4.w;
        float4 b4 = *reinterpret_cast<const float4*>(&B[(long long)(bn + lr) * ldb + k0 + lc]);
        Bs[lc + 0][lr] = b4.x; Bs[lc + 1][lr] = b4.y;
        Bs[lc + 2][lr] = b4.z; Bs[lc + 3][lr] = b4.w;
        __syncthreads();

        #pragma unroll
        for (int k = 0; k < BK; ++k) {
            float ra[4], rb[4];
            #pragma unroll
            for (int i = 0; i < 4; ++i) ra[i] = As[k][ty * 4 + i];
            #pragma unroll
            for (int j = 0; j < 4; ++j) rb[j] = Bs[k][tx * 4 + j];
            #pragma unroll
            for (int i = 0; i < 4; ++i)
                #pragma unroll
                for (int j = 0; j < 4; ++j)
                    acc[i][j] += ra[i] * rb[j];
        }
        __syncthreads();
    }

    #pragma unroll
    for (int i = 0; i < 4; ++i) {
        long long row = bm + ty * 4 + i;
        #pragma unroll
        for (int j = 0; j < 4; ++j)
            C[row * ldc + bn + tx * 4 + j] = acc[i][j];
    }
}

// C[M,N] = A[M,K] @ B[K,N]   (row-major; used for P @ V)
__global__ void gemm_nn(const float* __restrict__ A, const float* __restrict__ B,
                        float* __restrict__ C,
                        int M, int N, int K, int lda, int ldb, int ldc,
                        long long aBOff, long long bBOff, int bDiv, long long cBOff)
{
    int z = blockIdx.z;
    A += (long long)z * aBOff;
    B += (long long)(z / bDiv) * bBOff;
    C += (long long)z * cBOff;

    __shared__ float As[BK][BM + 4];
    __shared__ float Bs[BK][BN + 4];

    int tid = threadIdx.x;
    int bm = blockIdx.y * BM;
    int bn = blockIdx.x * BN;
    int tx = tid & 15;
    int ty = tid >> 4;

    int lr = tid >> 2;                // A: row within tile
    int lc = (tid & 3) * 4;           // A: k-chunk within tile
    int bk = tid >> 4;                // B: k-row within tile (0..15)
    int bq = (tid & 15) * 4;          // B: n-chunk within tile (0..60)

    float acc[4][4] = {};

    for (int k0 = 0; k0 < K; k0 += BK) {
        float4 a4 = *reinterpret_cast<const float4*>(&A[(long long)(bm + lr) * lda + k0 + lc]);
        As[lc + 0][lr] = a4.x; As[lc + 1][lr] = a4.y;
        As[lc + 2][lr] = a4.z; As[lc + 3][lr] = a4.w;
        float4 b4 = *reinterpret_cast<const float4*>(&B[(long long)(k0 + bk) * ldb + bn + bq]);
        Bs[bk][bq + 0] = b4.x; Bs[bk][bq + 1] = b4.y;
        Bs[bk][bq + 2] = b4.z; Bs[bk][bq + 3] = b4.w;
        __syncthreads();

        #pragma unroll
        for (int k = 0; k < BK; ++k) {
            float ra[4], rb[4];
            #pragma unroll
            for (int i = 0; i < 4; ++i) ra[i] = As[k][ty * 4 + i];
            #pragma unroll
            for (int j = 0; j < 4; ++j) rb[j] = Bs[k][tx * 4 + j];
            #pragma unroll
            for (int i = 0; i < 4; ++i)
                #pragma unroll
                for (int j = 0; j < 4; ++j)
                    acc[i][j] += ra[i] * rb[j];
        }
        __syncthreads();
    }

    #pragma unroll
    for (int i = 0; i < 4; ++i) {
        long long row = bm + ty * 4 + i;
        #pragma unroll
        for (int j = 0; j < 4; ++j)
            C[row * ldc + bn + tx * 4 + j] = acc[i][j];
    }
}

// ---------------- elementwise / norm kernels ----------------
__global__ void rmsnorm_kernel(const float* __restrict__ x, const float* __restrict__ w,
                               float* __restrict__ out)
{
    int row = blockIdx.x;
    const float* xr = x + (long long)row * DIM;
    __shared__ float red[256];
    int t = threadIdx.x;
    float s = 0.f;
    for (int i = t; i < DIM; i += 256) { float v = xr[i]; s += v * v; }
    red[t] = s; __syncthreads();
    for (int o = 128; o > 0; o >>= 1) { if (t < o) red[t] += red[t + o]; __syncthreads(); }
    float inv = rsqrtf(red[0] / (float)DIM + EPS);
    float* orow = out + (long long)row * DIM;
    for (int i = t; i < DIM; i += 256) orow[i] = xr[i] * inv * w[i];
}

// in-place layernorm(head_dim) + RoPE on q and k inside the qkv buffer.
// blockIdx.x = seq pos, blockIdx.y = 0..23 (0..15 q-heads, 16..23 k-heads), 128 threads.
__global__ void qknorm_rope_kernel(float* __restrict__ qkv,
                                   const float* __restrict__ qn_w, const float* __restrict__ qn_b,
                                   const float* __restrict__ kn_w, const float* __restrict__ kn_b,
                                   const float* __restrict__ fcos, const float* __restrict__ fsin)
{
    int s = blockIdx.x;
    int h = blockIdx.y;
    bool isq = (h < NH);
    int col = isq ? h * HD : NH * HD + (h - NH) * HD;
    float* p = qkv + (long long)s * QKV_DIM + col;
    const float* w = isq ? qn_w : kn_w;
    const float* b = isq ? qn_b : kn_b;

    int t = threadIdx.x;   // 0..127
    float v = p[t];

    __shared__ float sm[4], sv[4];
    float m = v;
    #pragma unroll
    for (int o = 16; o; o >>= 1) m += __shfl_xor_sync(0xffffffffu, m, o);
    if ((t & 31) == 0) sm[t >> 5] = m;
    __syncthreads();
    float mean = (sm[0] + sm[1] + sm[2] + sm[3]) * (1.f / HD);
    float d = v - mean;
    float vv = d * d;
    #pragma unroll
    for (int o = 16; o; o >>= 1) vv += __shfl_xor_sync(0xffffffffu, vv, o);
    if ((t & 31) == 0) sv[t >> 5] = vv;
    __syncthreads();
    float var = (sv[0] + sv[1] + sv[2] + sv[3]) * (1.f / HD);
    float n = d * rsqrtf(var + EPS) * w[t] + b[t];

    __shared__ float sh[HD];
    sh[t] = n; __syncthreads();

    float c  = fcos[(long long)s * (HD / 2) + (t >> 1)];
    float si = fsin[(long long)s * (HD / 2) + (t >> 1)];
    float x0 = sh[t & ~1];
    float x1 = sh[t | 1];
    p[t] = ((t & 1) == 0) ? (x0 * c - x1 * si) : (x0 * si + x1 * c);
}

// softmax over a 2048-long score row with scale + additive mask, in place.
__global__ void softmax_kernel(float* __restrict__ scores, const float* __restrict__ mask)
{
    int i = blockIdx.x;     // query position
    int h = blockIdx.y;     // head
    float* row = scores + ((long long)h * S + i) * S;
    const float* mrow = mask + (long long)i * S;
    const float sc = 0.08838834764831845f;   // 1/sqrt(128)

    __shared__ float red[256];
    int t = threadIdx.x;

    float mx = -1e30f;
    for (int j = t; j < S; j += 256) {
        float v = row[j] * sc + mrow[j];
        mx = fmaxf(mx, v);
    }
    red[t] = mx; __syncthreads();
    for (int o = 128; o > 0; o >>= 1) { if (t < o) red[t] = fmaxf(red[t], red[t + o]); __syncthreads(); }
    mx = red[0]; __syncthreads();

    float sum = 0.f;
    for (int j = t; j < S; j += 256) {
        float v = expf(row[j] * sc + mrow[j] - mx);
        row[j] = v;
        sum += v;
    }
    red[t] = sum; __syncthreads();
    for (int o = 128; o > 0; o >>= 1) { if (t < o) red[t] += red[t + o]; __syncthreads(); }
    float inv = 1.f / red[0];
    for (int j = t; j < S; j += 256) row[j] *= inv;
}

__global__ void add_kernel(const float* __restrict__ a, const float* __restrict__ b,
                           float* __restrict__ out, long long n)
{
    long long i = (long long)blockIdx.x * 256 + threadIdx.x;
    if (i < n) out[i] = a[i] + b[i];
}

__global__ void swiglu_kernel(const float* __restrict__ x13, float* __restrict__ gate)
{
    unsigned idx = blockIdx.x * 256u + threadIdx.x;
    if (idx >= (unsigned)(S * HID)) return;
    unsigned s = idx / HID;
    unsigned j = idx - s * HID;
    float a = x13[(size_t)s * (2 * HID) + j];
    float b = x13[(size_t)s * (2 * HID) + HID + j];
    float sig = 1.f / (1.f + expf(-a));
    gate[idx] = a * sig * b;
}

// ---------------- launcher ----------------
extern "C" void kernel_launch(void* const* d_in, const int* in_sizes, int n_in,
                              void* d_out, int out_size)
{
    const float* x           = (const float*)d_in[0];
    const float* fcos        = (const float*)d_in[1];
    const float* fsin        = (const float*)d_in[2];
    const float* mask        = (const float*)d_in[3];
    const float* wqkv        = (const float*)d_in[4];
    const float* wo          = (const float*)d_in[5];
    const float* qn_w        = (const float*)d_in[6];
    const float* qn_b        = (const float*)d_in[7];
    const float* kn_w        = (const float*)d_in[8];
    const float* kn_b        = (const float*)d_in[9];
    const float* attn_norm_w = (const float*)d_in[10];
    const float* ffn_norm_w  = (const float*)d_in[11];
    const float* w13         = (const float*)d_in[12];
    const float* w2          = (const float*)d_in[13];
    float* out = (float*)d_out;

    float *h, *qkv, *scores, *o, *tmp, *h2, *x13, *gate;
    cudaGetSymbolAddress((void**)&h,      g_h);
    cudaGetSymbolAddress((void**)&qkv,    g_qkv);
    cudaGetSymbolAddress((void**)&scores, g_scores);
    cudaGetSymbolAddress((void**)&o,      g_o);
    cudaGetSymbolAddress((void**)&tmp,    g_tmp);
    cudaGetSymbolAddress((void**)&h2,     g_h2);
    cudaGetSymbolAddress((void**)&x13,    g_x13);
    cudaGetSymbolAddress((void**)&gate,   g_gate);

    // 1) h = rmsnorm(x, attn_norm_w)
    rmsnorm_kernel<<<S, 256>>>(x, attn_norm_w, h);

    // 2) qkv = h @ wqkv^T    [2048, 4096]
    gemm_nt<<<dim3(QKV_DIM / BN, S / BM, 1), 256>>>(
        h, wqkv, qkv, S, QKV_DIM, DIM, DIM, DIM, QKV_DIM, 0, 0, 1, 0);

    // 3) per-head layernorm + RoPE on q,k (in place inside qkv)
    qknorm_rope_kernel<<<dim3(S, NH + NKV), HD>>>(qkv, qn_w, qn_b, kn_w, kn_b, fcos, fsin);

    // 4) scores[h] = q_h @ k_{h/2}^T   (M=N=2048, K=128), batched over 16 heads
    gemm_nt<<<dim3(S / BN, S / BM, NH), 256>>>(
        qkv, qkv + NH * HD, scores,
        S, S, HD, QKV_DIM, QKV_DIM, S,
        /*aBOff=*/HD, /*bBOff=*/HD, /*bDiv=*/2, /*cBOff=*/(long long)S * S);

    // 5) softmax(scale + mask), in place
    softmax_kernel<<<dim3(S, NH), 256>>>(scores, mask);

    // 6) o[:, h*128:(h+1)*128] = P_h @ v_{h/2}   (M=2048, N=128, K=2048)
    gemm_nn<<<dim3(HD / BN, S / BM, NH), 256>>>(
        scores, qkv + (NH + NKV) * HD, o,
        S, HD, S, S, QKV_DIM, DIM,
        /*aBOff=*/(long long)S * S, /*bBOff=*/HD, /*bDiv=*/2, /*cBOff=*/HD);

    // 7) attn = o @ wo^T
    gemm_nt<<<dim3(DIM / BN, S / BM, 1), 256>>>(
        o, wo, tmp, S, DIM, DIM, DIM, DIM, DIM, 0, 0, 1, 0);

    // 8) h2 = x + attn
    add_kernel<<<(S * DIM) / 256, 256>>>(x, tmp, h2, (long long)S * DIM);

    // 9) g = rmsnorm(h2, ffn_norm_w)   (reuse h buffer)
    rmsnorm_kernel<<<S, 256>>>(h2, ffn_norm_w, h);

    // 10) x13 = g @ w13^T   [2048, 11264]
    gemm_nt<<<dim3((2 * HID) / BN, S / BM, 1), 256>>>(
        h, w13, x13, S, 2 * HID, DIM, DIM, DIM, 2 * HID, 0, 0, 1, 0);

    // 11) gate = silu(x1) * x3
    swiglu_kernel<<<(S * HID + 255) / 256, 256>>>(x13, gate);

    // 12) ffn = gate @ w2^T
    gemm_nt<<<dim3(DIM / BN, S / BM, 1), 256>>>(
        gate, w2, tmp, S, DIM, HID, HID, HID, DIM, 0, 0, 1, 0);

    // 13) out = h2 + ffn
    add_kernel<<<(S * DIM) / 256, 256>>>(h2, tmp, out, (long long)S * DIM);
}

// round 2
// speedup vs baseline: 1.7476x; 1.7476x over previous
#include <cuda_runtime.h>
#include <math.h>

#define S 2048
#define DIM 2048
#define NH 16
#define NKV 8
#define HD 128
#define HID 5632
#define QKV_DIM ((NH + 2*NKV) * HD)   // 4096
#define EPS 1e-5f

// ---------------- scratch ----------------
__device__ float g_h[(size_t)S * DIM];
__device__ float g_qkv[(size_t)S * QKV_DIM];
__device__ float g_scores[(size_t)NH * S * S];
__device__ float g_o[(size_t)S * DIM];
__device__ float g_tmp[(size_t)S * DIM];
__device__ float g_h2[(size_t)S * DIM];
__device__ float g_x13[(size_t)S * 2 * HID];
__device__ float g_gate[(size_t)S * HID];

// ---------------- tf32 tensor-core GEMM ----------------
// C[M,N] = A[M,K] @ op(B), all row-major fp32.
// BT=true : B is [N,K] (NT GEMM).  BT=false : B is [K,N] (NN GEMM).
// Fragment-packed smem: global->smem scatters into mma fragment order, so the
// compute loop reads each A fragment with one LDS.128 and each B fragment with
// one LDS.64, conflict-free.
#define BM 128
#define BN 128
#define BK 32

__device__ __forceinline__ float f2tf(float f) {
    unsigned u; asm("cvt.rna.tf32.f32 %0, %1;" : "=r"(u) : "f"(f));
    return __uint_as_float(u);
}

__device__ __forceinline__ void mma_tf32(float* c, uint4 a, uint2 b) {
    asm volatile(
        "mma.sync.aligned.m16n8k8.row.col.f32.tf32.tf32.f32 "
        "{%0,%1,%2,%3}, {%4,%5,%6,%7}, {%8,%9}, {%0,%1,%2,%3};"
        : "+f"(c[0]), "+f"(c[1]), "+f"(c[2]), "+f"(c[3])
        : "r"(a.x), "r"(a.y), "r"(a.z), "r"(a.w), "r"(b.x), "r"(b.y));
}

// causalMode: 0 = none, 1 = skip blocks with bn > bm (scores), 2 = k-loop limited to bm+BM (PV)
template<bool BT>
__global__ void __launch_bounds__(256, 2)
gemm_tc(const float* __restrict__ A, const float* __restrict__ B, float* __restrict__ C,
        int M, int N, int K, int lda, int ldb, int ldc,
        long long aBOff, long long bBOff, int bDiv, long long cBOff, int causalMode)
{
    int bm = blockIdx.y * BM;
    int bn = blockIdx.x * BN;
    if (causalMode == 1 && bn > bm) return;

    int z = blockIdx.z;
    A += (long long)z * aBOff;
    B += (long long)(z / bDiv) * bBOff;
    C += (long long)z * cBOff;

    int kmax  = (causalMode == 2) ? (bm + BM) : K;
    int nIter = kmax / BK;

    extern __shared__ float smem[];
    // per stage: A frags 4096 floats, B frags 4096 floats
    const int STAGE = 8192;

    int tid  = threadIdx.x;
    int lane = tid & 31;
    int warp = tid >> 5;
    int wm = warp >> 2;        // 0..1
    int wn = warp & 3;         // 0..3

    // global A: thread covers row = tid>>1, cols [(tid&1)*16 + q*4, +4)
    int arow  = tid >> 1;
    int acol0 = (tid & 1) * 16;

    const float* Abase = A + (long long)(bm + arow) * lda + acol0;
    const float* Bbase;
    if (BT) Bbase = B + (long long)(bn + arow) * ldb + acol0;   // B[N,K]: row = bn+arow
    else    Bbase = B;                                          // B[K,N]

    float4 aReg[4], bReg[4];

    // precomputed A packing offsets (floats)
    int aOff[4];
    {
        int i  = arow >> 4;
        int mm = arow & 15;
        #pragma unroll
        for (int q = 0; q < 4; ++q) {
            int lk  = acol0 + q * 4;
            int s   = lk >> 3;
            int reg = ((mm >> 3) & 1) + (((lk >> 2) & 1) << 1);
            aOff[q] = ((i * 4 + s) * 32 + ((mm & 7) << 2)) * 4 + reg;
        }
    }
    int bOff[4];
    if (BT) {
        int j  = arow >> 3;
        int nn = arow & 7;
        #pragma unroll
        for (int q = 0; q < 4; ++q) {
            int lk  = acol0 + q * 4;
            int s   = lk >> 3;
            int reg = (lk >> 2) & 1;
            bOff[q] = ((j * 4 + s) * 32 + (nn << 2)) * 2 + reg;
        }
    } else {
        #pragma unroll
        for (int q = 0; q < 4; ++q) {
            int idx = tid + 256 * q;
            int lk  = idx >> 5;            // 0..31
            int ln0 = (idx & 31) * 4;      // 0..124
            int j   = ln0 >> 3;
            int s   = lk >> 3;
            int reg = (lk >> 2) & 1;
            int lane0 = ((ln0 & 7) << 2) | (lk & 3);
            bOff[q] = ((j * 4 + s) * 32 + lane0) * 2 + reg;
        }
    }

    float acc[4][4][4];
    #pragma unroll
    for (int a = 0; a < 4; ++a)
        #pragma unroll
        for (int b = 0; b < 4; ++b)
            #pragma unroll
            for (int c = 0; c < 4; ++c) acc[a][b][c] = 0.f;

    // ---- load tile k0 into registers ----
    auto loadTiles = [&](int k0) {
        #pragma unroll
        for (int q = 0; q < 4; ++q)
            aReg[q] = *reinterpret_cast<const float4*>(Abase + k0 + q * 4);
        if (BT) {
            #pragma unroll
            for (int q = 0; q < 4; ++q)
                bReg[q] = *reinterpret_cast<const float4*>(Bbase + k0 + q * 4);
        } else {
            #pragma unroll
            for (int q = 0; q < 4; ++q) {
                int idx = tid + 256 * q;
                int lk  = idx >> 5;
                int ln0 = (idx & 31) * 4;
                bReg[q] = *reinterpret_cast<const float4*>(
                    Bbase + (long long)(k0 + lk) * ldb + bn + ln0);
            }
        }
    };

    auto storeTiles = [&](int stage) {
        float* sA = smem + stage * STAGE;
        float* sB = sA + 4096;
        #pragma unroll
        for (int q = 0; q < 4; ++q) {
            float* p = sA + aOff[q];
            p[0]  = f2tf(aReg[q].x);
            p[4]  = f2tf(aReg[q].y);
            p[8]  = f2tf(aReg[q].z);
            p[12] = f2tf(aReg[q].w);
        }
        if (BT) {
            #pragma unroll
            for (int q = 0; q < 4; ++q) {
                float* p = sB + bOff[q];
                p[0] = f2tf(bReg[q].x);
                p[2] = f2tf(bReg[q].y);
                p[4] = f2tf(bReg[q].z);
                p[6] = f2tf(bReg[q].w);
            }
        } else {
            #pragma unroll
            for (int q = 0; q < 4; ++q) {
                float* p = sB + bOff[q];
                p[0]  = f2tf(bReg[q].x);
                p[8]  = f2tf(bReg[q].y);
                p[16] = f2tf(bReg[q].z);
                p[24] = f2tf(bReg[q].w);
            }
        }
    };

    loadTiles(0);
    storeTiles(0);
    __syncthreads();

    for (int it = 0; it < nIter; ++it) {
        int cur = it & 1;
        bool more = (it + 1 < nIter);
        if (more) loadTiles((it + 1) * BK);

        const float* sA = smem + cur * STAGE;
        const float* sB = sA + 4096;

        #pragma unroll
        for (int s = 0; s < 4; ++s) {
            uint4 af[4];
            uint2 bf[4];
            #pragma unroll
            for (int mi = 0; mi < 4; ++mi)
                af[mi] = *reinterpret_cast<const uint4*>(
                    sA + ((((wm * 4 + mi) * 4 + s) * 32 + lane) << 2));
            #pragma unroll
            for (int nj = 0; nj < 4; ++nj)
                bf[nj] = *reinterpret_cast<const uint2*>(
                    sB + ((((wn * 4 + nj) * 4 + s) * 32 + lane) << 1));
            #pragma unroll
            for (int mi = 0; mi < 4; ++mi)
                #pragma unroll
                for (int nj = 0; nj < 4; ++nj)
                    mma_tf32(acc[mi][nj], af[mi], bf[nj]);
        }

        if (more) {
            storeTiles(cur ^ 1);
            __syncthreads();
        }
    }

    // ---- epilogue ----
    int grp = lane >> 2;
    int tg  = lane & 3;
    #pragma unroll
    for (int mi = 0; mi < 4; ++mi) {
        long long r0 = bm + wm * 64 + mi * 16 + grp;
        #pragma unroll
        for (int nj = 0; nj < 4; ++nj) {
            int c0 = bn + wn * 32 + nj * 8 + tg * 2;
            float2 v01 = make_float2(acc[mi][nj][0], acc[mi][nj][1]);
            float2 v23 = make_float2(acc[mi][nj][2], acc[mi][nj][3]);
            *reinterpret_cast<float2*>(&C[r0 * ldc + c0])       = v01;
            *reinterpret_cast<float2*>(&C[(r0 + 8) * ldc + c0]) = v23;
        }
    }
}

// ---------------- elementwise / norm kernels ----------------
__global__ void rmsnorm_kernel(const float* __restrict__ x, const float* __restrict__ w,
                               float* __restrict__ out)
{
    int row = blockIdx.x;
    const float* xr = x + (long long)row * DIM;
    __shared__ float red[256];
    int t = threadIdx.x;
    float s = 0.f;
    for (int i = t; i < DIM; i += 256) { float v = xr[i]; s += v * v; }
    red[t] = s; __syncthreads();
    for (int o = 128; o > 0; o >>= 1) { if (t < o) red[t] += red[t + o]; __syncthreads(); }
    float inv = rsqrtf(red[0] / (float)DIM + EPS);
    float* orow = out + (long long)row * DIM;
    for (int i = t; i < DIM; i += 256) orow[i] = xr[i] * inv * w[i];
}

__global__ void qknorm_rope_kernel(float* __restrict__ qkv,
                                   const float* __restrict__ qn_w, const float* __restrict__ qn_b,
                                   const float* __restrict__ kn_w, const float* __restrict__ kn_b,
                                   const float* __restrict__ fcos, const float* __restrict__ fsin)
{
    int s = blockIdx.x;
    int h = blockIdx.y;
    bool isq = (h < NH);
    int col = isq ? h * HD : NH * HD + (h - NH) * HD;
    float* p = qkv + (long long)s * QKV_DIM + col;
    const float* w = isq ? qn_w : kn_w;
    const float* b = isq ? qn_b : kn_b;

    int t = threadIdx.x;
    float v = p[t];

    __shared__ float sm[4], sv[4];
    float m = v;
    #pragma unroll
    for (int o = 16; o; o >>= 1) m += __shfl_xor_sync(0xffffffffu, m, o);
    if ((t & 31) == 0) sm[t >> 5] = m;
    __syncthreads();
    float mean = (sm[0] + sm[1] + sm[2] + sm[3]) * (1.f / HD);
    float d = v - mean;
    float vv = d * d;
    #pragma unroll
    for (int o = 16; o; o >>= 1) vv += __shfl_xor_sync(0xffffffffu, vv, o);
    if ((t & 31) == 0) sv[t >> 5] = vv;
    __syncthreads();
    float var = (sv[0] + sv[1] + sv[2] + sv[3]) * (1.f / HD);
    float n = d * rsqrtf(var + EPS) * w[t] + b[t];

    __shared__ float sh[HD];
    sh[t] = n; __syncthreads();

    float c  = fcos[(long long)s * (HD / 2) + (t >> 1)];
    float si = fsin[(long long)s * (HD / 2) + (t >> 1)];
    float x0 = sh[t & ~1];
    float x1 = sh[t | 1];
    p[t] = ((t & 1) == 0) ? (x0 * c - x1 * si) : (x0 * si + x1 * c);
}

// causal softmax: reads j<=i, writes zeros in (i, 128-aligned block end). Mask
// implied (causal), garbage from skipped upper score blocks never touched.
__global__ void softmax_causal(float* __restrict__ scores)
{
    int i = blockIdx.x;
    int h = blockIdx.y;
    float* row = scores + ((long long)h * S + i) * S;
    const float sc = 0.08838834764831845f;   // 1/sqrt(128)
    int lim = ((i >> 7) + 1) << 7;            // write limit (block boundary)

    __shared__ float red[256];
    int t = threadIdx.x;

    float mx = -1e30f;
    for (int j = t; j <= i; j += 256) mx = fmaxf(mx, row[j] * sc);
    red[t] = mx; __syncthreads();
    for (int o = 128; o > 0; o >>= 1) { if (t < o) red[t] = fmaxf(red[t], red[t + o]); __syncthreads(); }
    mx = red[0]; __syncthreads();

    float sum = 0.f;
    for (int j = t; j <= i; j += 256) {
        float v = expf(row[j] * sc - mx);
        row[j] = v;
        sum += v;
    }
    red[t] = sum; __syncthreads();
    for (int o = 128; o > 0; o >>= 1) { if (t < o) red[t] += red[t + o]; __syncthreads(); }
    float inv = 1.f / red[0];
    for (int j = t; j < lim; j += 256) row[j] = (j <= i) ? row[j] * inv : 0.f;
}

__global__ void add_kernel(const float* __restrict__ a, const float* __restrict__ b,
                           float* __restrict__ out, long long n)
{
    long long i = (long long)blockIdx.x * 256 + threadIdx.x;
    if (i < n) out[i] = a[i] + b[i];
}

__global__ void swiglu_kernel(const float* __restrict__ x13, float* __restrict__ gate)
{
    unsigned idx = blockIdx.x * 256u + threadIdx.x;
    if (idx >= (unsigned)(S * HID)) return;
    unsigned s = idx / HID;
    unsigned j = idx - s * HID;
    float a = x13[(size_t)s * (2 * HID) + j];
    float b = x13[(size_t)s * (2 * HID) + HID + j];
    float sig = 1.f / (1.f + expf(-a));
    gate[idx] = a * sig * b;
}

// ---------------- launcher ----------------
extern "C" void kernel_launch(void* const* d_in, const int* in_sizes, int n_in,
                              void* d_out, int out_size)
{
    const float* x           = (const float*)d_in[0];
    const float* fcos        = (const float*)d_in[1];
    const float* fsin        = (const float*)d_in[2];
    // d_in[3] = mask (unused: causal handled analytically)
    const float* wqkv        = (const float*)d_in[4];
    const float* wo          = (const float*)d_in[5];
    const float* qn_w        = (const float*)d_in[6];
    const float* qn_b        = (const float*)d_in[7];
    const float* kn_w        = (const float*)d_in[8];
    const float* kn_b        = (const float*)d_in[9];
    const float* attn_norm_w = (const float*)d_in[10];
    const float* ffn_norm_w  = (const float*)d_in[11];
    const float* w13         = (const float*)d_in[12];
    const float* w2          = (const float*)d_in[13];
    float* out = (float*)d_out;

    float *h, *qkv, *scores, *o, *tmp, *h2, *x13, *gate;
    cudaGetSymbolAddress((void**)&h,      g_h);
    cudaGetSymbolAddress((void**)&qkv,    g_qkv);
    cudaGetSymbolAddress((void**)&scores, g_scores);
    cudaGetSymbolAddress((void**)&o,      g_o);
    cudaGetSymbolAddress((void**)&tmp,    g_tmp);
    cudaGetSymbolAddress((void**)&h2,     g_h2);
    cudaGetSymbolAddress((void**)&x13,    g_x13);
    cudaGetSymbolAddress((void**)&gate,   g_gate);

    const int SMEM = 2 * 8192 * 4;   // 64 KB
    cudaFuncSetAttribute(gemm_tc<true>,  cudaFuncAttributeMaxDynamicSharedMemorySize, SMEM);
    cudaFuncSetAttribute(gemm_tc<false>, cudaFuncAttributeMaxDynamicSharedMemorySize, SMEM);

    // 1) h = rmsnorm(x)
    rmsnorm_kernel<<<S, 256>>>(x, attn_norm_w, h);

    // 2) qkv = h @ wqkv^T
    gemm_tc<true><<<dim3(QKV_DIM / BN, S / BM, 1), 256, SMEM>>>(
        h, wqkv, qkv, S, QKV_DIM, DIM, DIM, DIM, QKV_DIM, 0, 0, 1, 0, 0);

    // 3) q/k layernorm + rope, in place
    qknorm_rope_kernel<<<dim3(S, NH + NKV), HD>>>(qkv, qn_w, qn_b, kn_w, kn_b, fcos, fsin);

    // 4) scores = q @ k^T (causal: upper blocks skipped)
    gemm_tc<true><<<dim3(S / BN, S / BM, NH), 256, SMEM>>>(
        qkv, qkv + NH * HD, scores,
        S, S, HD, QKV_DIM, QKV_DIM, S,
        HD, HD, 2, (long long)S * S, 1);

    // 5) causal softmax (in place)
    softmax_causal<<<dim3(S, NH), 256>>>(scores);

    // 6) o_h = P_h @ v_{h/2}  (k-loop clamped at causal boundary)
    gemm_tc<false><<<dim3(HD / BN, S / BM, NH), 256, SMEM>>>(
        scores, qkv + (NH + NKV) * HD, o,
        S, HD, S, S, QKV_DIM, DIM,
        (long long)S * S, HD, 2, HD, 2);

    // 7) attn = o @ wo^T
    gemm_tc<true><<<dim3(DIM / BN, S / BM, 1), 256, SMEM>>>(
        o, wo, tmp, S, DIM, DIM, DIM, DIM, DIM, 0, 0, 1, 0, 0);

    // 8) h2 = x + attn
    add_kernel<<<(S * DIM) / 256, 256>>>(x, tmp, h2, (long long)S * DIM);

    // 9) g = rmsnorm(h2)
    rmsnorm_kernel<<<S, 256>>>(h2, ffn_norm_w, h);

    // 10) x13 = g @ w13^T
    gemm_tc<true><<<dim3((2 * HID) / BN, S / BM, 1), 256, SMEM>>>(
        h, w13, x13, S, 2 * HID, DIM, DIM, DIM, 2 * HID, 0, 0, 1, 0, 0);

    // 11) gate = silu(x1) * x3
    swiglu_kernel<<<(S * HID + 255) / 256, 256>>>(x13, gate);

    // 12) ffn = gate @ w2^T
    gemm_tc<true><<<dim3(DIM / BN, S / BM, 1), 256, SMEM>>>(
        gate, w2, tmp, S, DIM, HID, HID, HID, DIM, 0, 0, 1, 0, 0);

    // 13) out = h2 + ffn
    add_kernel<<<(S * DIM) / 256, 256>>>(h2, tmp, out, (long long)S * DIM);
}

// round 4
// speedup vs baseline: 5.2408x; 2.9989x over previous
#include <cuda_runtime.h>
#include <cuda_fp16.h>
#include <math.h>
#include <stdint.h>

#define S 2048
#define DIM 2048
#define NH 16
#define NKV 8
#define HD 128
#define HID 5632
#define QKV_DIM ((NH + 2*NKV) * HD)   // 4096
#define VOFF ((NH + NKV) * HD)        // 3072
#define EPS 1e-5f

// ---------------- scratch ----------------
__device__ float g_h[(size_t)S * DIM];
__device__ float g_qkv[(size_t)S * QKV_DIM];
__device__ float g_scores[(size_t)NH * S * S];
__device__ float g_o[(size_t)S * DIM];
__device__ float g_tmp[(size_t)S * DIM];
__device__ float g_h2[(size_t)S * DIM];
__device__ float g_x13[(size_t)S * 2 * HID];
__device__ float g_gate[(size_t)S * HID];
__device__ float g_vt[(size_t)NKV * HD * S];   // V transposed: [kv*HD + d][s]

// ---------------- helpers ----------------
__device__ __forceinline__ uint32_t sm2u(const void* p) {
    uint32_t a;
    asm("{ .reg .u64 t; cvta.to.shared.u64 t, %1; cvt.u32.u64 %0, t; }" : "=r"(a) : "l"(p));
    return a;
}

// fp16 smem tile offset: rows pairs share a 128B line; 8x16B segments XOR-swizzled.
// tile is [128 rows][32 halves], 8KB.
__device__ __forceinline__ uint32_t smoff(uint32_t m, uint32_t k) {
    return (m >> 1) * 128u
         + (((((m & 1u) << 2) | (k >> 3)) ^ ((m >> 1) & 7u)) << 4)
         + (k & 7u) * 2u;
}

__device__ __forceinline__ uint4 ldm4(uint32_t addr) {
    uint4 r;
    asm volatile("ldmatrix.sync.aligned.m8n8.x4.shared.b16 {%0,%1,%2,%3}, [%4];"
                 : "=r"(r.x), "=r"(r.y), "=r"(r.z), "=r"(r.w) : "r"(addr));
    return r;
}

__device__ __forceinline__ void mma_f16(float* c, const uint4& a, uint32_t b0, uint32_t b1) {
    asm volatile(
        "mma.sync.aligned.m16n8k16.row.col.f32.f16.f16.f32 "
        "{%0,%1,%2,%3}, {%4,%5,%6,%7}, {%8,%9}, {%0,%1,%2,%3};"
        : "+f"(c[0]), "+f"(c[1]), "+f"(c[2]), "+f"(c[3])
        : "r"(a.x), "r"(a.y), "r"(a.z), "r"(a.w), "r"(b0), "r"(b1));
}

__device__ __forceinline__ uint4 cvt8(float4 f0, float4 f1) {
    __half2 h0 = __floats2half2_rn(f0.x, f0.y);
    __half2 h1 = __floats2half2_rn(f0.z, f0.w);
    __half2 h2 = __floats2half2_rn(f1.x, f1.y);
    __half2 h3 = __floats2half2_rn(f1.z, f1.w);
    uint4 u;
    u.x = *reinterpret_cast<uint32_t*>(&h0);
    u.y = *reinterpret_cast<uint32_t*>(&h1);
    u.z = *reinterpret_cast<uint32_t*>(&h2);
    u.w = *reinterpret_cast<uint32_t*>(&h3);
    return u;
}

__device__ __forceinline__ void sts16(uint32_t addr, uint4 v) {
    asm volatile("st.shared.v4.b32 [%0], {%1,%2,%3,%4};"
                 :: "r"(addr), "r"(v.x), "r"(v.y), "r"(v.z), "r"(v.w) : "memory");
}

// ---------------- fp16 mma.sync NT GEMM ----------------
// C[M,N] = A[M,K] @ B[N,K]^T, row-major fp32 in/out, fp16 compute, fp32 accum.
// Tile 128x128x32, 8 warps (2x4), warp tile 64x32. Double-buffered smem.
// causalMode: 0 none, 1 skip bn>bm (scores), 2 clamp K at bm+128 (PV).
#define BM 128
#define BN 128
#define BK 32
#define TILE_B 8192            // one operand tile bytes (128x32 fp16)
#define STAGE_B (2 * TILE_B)   // 16KB per stage

__global__ void __launch_bounds__(256, 2)
gemm_f16(const float* __restrict__ A, const float* __restrict__ B, float* __restrict__ C,
         int K, int lda, int ldb, int ldc,
         long long aBOff, long long bBOff, int bDiv, long long cBOff, int causalMode)
{
    int bm = blockIdx.x * BM;
    int bn = blockIdx.y * BN;
    if (causalMode == 1 && bn > bm) return;

    int z = blockIdx.z;
    A += (long long)z * aBOff;
    B += (long long)(z / bDiv) * bBOff;
    C += (long long)z * cBOff;

    __shared__ __align__(1024) unsigned char smem[2 * STAGE_B];
    uint32_t smB = sm2u(smem);

    int tid  = threadIdx.x;
    int lane = tid & 31;
    int warp = tid >> 5;
    int wm = warp >> 2;   // 0..1
    int wn = warp & 3;    // 0..3

    int kmax = (causalMode == 2) ? (bm + BM) : K;
    int nCh  = kmax / BK;

    // ---- producer mapping: thread -> (row, 8-float k chunk); 2 chunks each for A,B
    int mA  = tid >> 2;          // 0..63
    int kcA = (tid & 3) * 8;     // 0,8,16,24
    const float* Ag0 = A + (long long)(bm + mA)      * lda + kcA;
    const float* Ag1 = A + (long long)(bm + mA + 64) * lda + kcA;
    const float* Bg0 = B + (long long)(bn + mA)      * ldb + kcA;
    const float* Bg1 = B + (long long)(bn + mA + 64) * ldb + kcA;
    uint32_t st0 = smoff(mA, kcA);
    uint32_t st1 = smoff(mA + 64, kcA);

    // ---- consumer ldmatrix base addresses (ks=0; ks=1 is XOR 32)
    uint32_t aAdr[4], bAdr[2];
    {
        int mi = lane >> 3;
        int ra = (lane & 7) + (mi & 1) * 8;
        int ka = (mi >> 1) * 8;
        #pragma unroll
        for (int g = 0; g < 4; ++g) aAdr[g] = smoff(wm * 64 + g * 16 + ra, ka);
        int rb = (lane & 7) + (mi >> 1) * 8;
        int kb = (mi & 1) * 8;
        #pragma unroll
        for (int g = 0; g < 2; ++g) bAdr[g] = smoff(wn * 32 + g * 16 + rb, kb);
    }

    float acc[4][4][4];
    #pragma unroll
    for (int a = 0; a < 4; ++a)
        #pragma unroll
        for (int b = 0; b < 4; ++b)
            #pragma unroll
            for (int c = 0; c < 4; ++c) acc[a][b][c] = 0.f;

    uint4 sA0, sA1, sB0, sB1;

    auto loadCvt = [&](int k0) {
        sA0 = cvt8(*reinterpret_cast<const float4*>(Ag0 + k0),
                   *reinterpret_cast<const float4*>(Ag0 + k0 + 4));
        sA1 = cvt8(*reinterpret_cast<const float4*>(Ag1 + k0),
                   *reinterpret_cast<const float4*>(Ag1 + k0 + 4));
        sB0 = cvt8(*reinterpret_cast<const float4*>(Bg0 + k0),
                   *reinterpret_cast<const float4*>(Bg0 + k0 + 4));
        sB1 = cvt8(*reinterpret_cast<const float4*>(Bg1 + k0),
                   *reinterpret_cast<const float4*>(Bg1 + k0 + 4));
    };
    auto storeStage = [&](int st) {
        uint32_t aB = smB + st * STAGE_B;
        uint32_t bB = aB + TILE_B;
        sts16(aB + st0, sA0);
        sts16(aB + st1, sA1);
        sts16(bB + st0, sB0);
        sts16(bB + st1, sB1);
    };

    loadCvt(0);
    storeStage(0);
    __syncthreads();

    for (int it = 0; it < nCh; ++it) {
        bool more = (it + 1 < nCh);
        if (more) loadCvt((it + 1) * BK);

        uint32_t aB = smB + (it & 1) * STAGE_B;
        uint32_t bB = aB + TILE_B;

        #pragma unroll
        for (int ks = 0; ks < 2; ++ks) {
            uint32_t kx = ks ? 32u : 0u;
            uint4 av[4], bv[2];
            #pragma unroll
            for (int g = 0; g < 4; ++g) av[g] = ldm4(aB + (aAdr[g] ^ kx));
            #pragma unroll
            for (int g = 0; g < 2; ++g) bv[g] = ldm4(bB + (bAdr[g] ^ kx));
            #pragma unroll
            for (int mi = 0; mi < 4; ++mi) {
                #pragma unroll
                for (int nj = 0; nj < 4; ++nj) {
                    uint32_t b0 = (nj & 1) ? bv[nj >> 1].z : bv[nj >> 1].x;
                    uint32_t b1 = (nj & 1) ? bv[nj >> 1].w : bv[nj >> 1].y;
                    mma_f16(acc[mi][nj], av[mi], b0, b1);
                }
            }
        }

        if (more) {
            storeStage((it + 1) & 1);
            __syncthreads();
        }
    }

    // ---- epilogue
    int grp = lane >> 2;
    int tg  = lane & 3;
    #pragma unroll
    for (int mi = 0; mi < 4; ++mi) {
        long long r0 = bm + wm * 64 + mi * 16 + grp;
        #pragma unroll
        for (int nj = 0; nj < 4; ++nj) {
            int c0 = bn + wn * 32 + nj * 8 + tg * 2;
            *reinterpret_cast<float2*>(&C[r0 * ldc + c0]) =
                make_float2(acc[mi][nj][0], acc[mi][nj][1]);
            *reinterpret_cast<float2*>(&C[(r0 + 8) * ldc + c0]) =
                make_float2(acc[mi][nj][2], acc[mi][nj][3]);
        }
    }
}

// ---------------- V transpose ----------------
__global__ void transpose_v(const float* __restrict__ qkv, float* __restrict__ vt)
{
    __shared__ float t[32][33];
    int s0 = blockIdx.x * 32;
    int d0 = blockIdx.y * 32;
    int tx = threadIdx.x, ty = threadIdx.y;   // 32 x 8
    #pragma unroll
    for (int j = 0; j < 32; j += 8)
        t[ty + j][tx] = qkv[(long long)(s0 + ty + j) * QKV_DIM + VOFF + d0 + tx];
    __syncthreads();
    #pragma unroll
    for (int j = 0; j < 32; j += 8)
        vt[(long long)(d0 + ty + j) * S + s0 + tx] = t[tx][ty + j];
}

// ---------------- elementwise / norm kernels ----------------
__global__ void rmsnorm_kernel(const float* __restrict__ x, const float* __restrict__ w,
                               float* __restrict__ out)
{
    int row = blockIdx.x;
    const float* xr = x + (long long)row * DIM;
    __shared__ float red[256];
    int t = threadIdx.x;
    float s = 0.f;
    for (int i = t; i < DIM; i += 256) { float v = xr[i]; s += v * v; }
    red[t] = s; __syncthreads();
    for (int o = 128; o > 0; o >>= 1) { if (t < o) red[t] += red[t + o]; __syncthreads(); }
    float inv = rsqrtf(red[0] / (float)DIM + EPS);
    float* orow = out + (long long)row * DIM;
    for (int i = t; i < DIM; i += 256) orow[i] = xr[i] * inv * w[i];
}

__global__ void qknorm_rope_kernel(float* __restrict__ qkv,
                                   const float* __restrict__ qn_w, const float* __restrict__ qn_b,
                                   const float* __restrict__ kn_w, const float* __restrict__ kn_b,
                                   const float* __restrict__ fcos, const float* __restrict__ fsin)
{
    int s = blockIdx.x;
    int h = blockIdx.y;
    bool isq = (h < NH);
    int col = isq ? h * HD : NH * HD + (h - NH) * HD;
    float* p = qkv + (long long)s * QKV_DIM + col;
    const float* w = isq ? qn_w : kn_w;
    const float* b = isq ? qn_b : kn_b;

    int t = threadIdx.x;
    float v = p[t];

    __shared__ float sm[4], sv[4];
    float m = v;
    #pragma unroll
    for (int o = 16; o; o >>= 1) m += __shfl_xor_sync(0xffffffffu, m, o);
    if ((t & 31) == 0) sm[t >> 5] = m;
    __syncthreads();
    float mean = (sm[0] + sm[1] + sm[2] + sm[3]) * (1.f / HD);
    float d = v - mean;
    float vv = d * d;
    #pragma unroll
    for (int o = 16; o; o >>= 1) vv += __shfl_xor_sync(0xffffffffu, vv, o);
    if ((t & 31) == 0) sv[t >> 5] = vv;
    __syncthreads();
    float var = (sv[0] + sv[1] + sv[2] + sv[3]) * (1.f / HD);
    float n = d * rsqrtf(var + EPS) * w[t] + b[t];

    __shared__ float sh[HD];
    sh[t] = n; __syncthreads();

    float c  = fcos[(long long)s * (HD / 2) + (t >> 1)];
    float si = fsin[(long long)s * (HD / 2) + (t >> 1)];
    float x0 = sh[t & ~1];
    float x1 = sh[t | 1];
    p[t] = ((t & 1) == 0) ? (x0 * c - x1 * si) : (x0 * si + x1 * c);
}

__global__ void softmax_causal(float* __restrict__ scores)
{
    int i = blockIdx.x;
    int h = blockIdx.y;
    float* row = scores + ((long long)h * S + i) * S;
    const float sc = 0.08838834764831845f;
    int lim = ((i >> 7) + 1) << 7;

    __shared__ float red[256];
    int t = threadIdx.x;

    float mx = -1e30f;
    for (int j = t; j <= i; j += 256) mx = fmaxf(mx, row[j] * sc);
    red[t] = mx; __syncthreads();
    for (int o = 128; o > 0; o >>= 1) { if (t < o) red[t] = fmaxf(red[t], red[t + o]); __syncthreads(); }
    mx = red[0]; __syncthreads();

    float sum = 0.f;
    for (int j = t; j <= i; j += 256) {
        float v = expf(row[j] * sc - mx);
        row[j] = v;
        sum += v;
    }
    red[t] = sum; __syncthreads();
    for (int o = 128; o > 0; o >>= 1) { if (t < o) red[t] += red[t + o]; __syncthreads(); }
    float inv = 1.f / red[0];
    for (int j = t; j < lim; j += 256) row[j] = (j <= i) ? row[j] * inv : 0.f;
}

__global__ void add_kernel(const float* __restrict__ a, const float* __restrict__ b,
                           float* __restrict__ out, long long n)
{
    long long i = (long long)blockIdx.x * 256 + threadIdx.x;
    if (i < n) out[i] = a[i] + b[i];
}

__global__ void swiglu_kernel(const float* __restrict__ x13, float* __restrict__ gate)
{
    unsigned idx = blockIdx.x * 256u + threadIdx.x;
    if (idx >= (unsigned)(S * HID)) return;
    unsigned s = idx / HID;
    unsigned j = idx - s * HID;
    float a = x13[(size_t)s * (2 * HID) + j];
    float b = x13[(size_t)s * (2 * HID) + HID + j];
    float sig = 1.f / (1.f + expf(-a));
    gate[idx] = a * sig * b;
}

// ---------------- launcher ----------------
extern "C" void kernel_launch(void* const* d_in, const int* in_sizes, int n_in,
                              void* d_out, int out_size)
{
    const float* x           = (const float*)d_in[0];
    const float* fcos        = (const float*)d_in[1];
    const float* fsin        = (const float*)d_in[2];
    const float* wqkv        = (const float*)d_in[4];
    const float* wo          = (const float*)d_in[5];
    const float* qn_w        = (const float*)d_in[6];
    const float* qn_b        = (const float*)d_in[7];
    const float* kn_w        = (const float*)d_in[8];
    const float* kn_b        = (const float*)d_in[9];
    const float* attn_norm_w = (const float*)d_in[10];
    const float* ffn_norm_w  = (const float*)d_in[11];
    const float* w13         = (const float*)d_in[12];
    const float* w2          = (const float*)d_in[13];
    float* out = (float*)d_out;

    float *h, *qkv, *scores, *o, *tmp, *h2, *x13, *gate, *vt;
    cudaGetSymbolAddress((void**)&h,      g_h);
    cudaGetSymbolAddress((void**)&qkv,    g_qkv);
    cudaGetSymbolAddress((void**)&scores, g_scores);
    cudaGetSymbolAddress((void**)&o,      g_o);
    cudaGetSymbolAddress((void**)&tmp,    g_tmp);
    cudaGetSymbolAddress((void**)&h2,     g_h2);
    cudaGetSymbolAddress((void**)&x13,    g_x13);
    cudaGetSymbolAddress((void**)&gate,   g_gate);
    cudaGetSymbolAddress((void**)&vt,     g_vt);

    // 1) h = rmsnorm(x)
    rmsnorm_kernel<<<S, 256>>>(x, attn_norm_w, h);

    // 2) qkv = h @ wqkv^T
    gemm_f16<<<dim3(S / BM, QKV_DIM / BN, 1), 256>>>(
        h, wqkv, qkv, DIM, DIM, DIM, QKV_DIM, 0, 0, 1, 0, 0);

    // 3) q/k layernorm + rope (in place)
    qknorm_rope_kernel<<<dim3(S, NH + NKV), HD>>>(qkv, qn_w, qn_b, kn_w, kn_b, fcos, fsin);

    // 4) vt = V^T
    transpose_v<<<dim3(S / 32, (NKV * HD) / 32), dim3(32, 8)>>>(qkv, vt);

    // 5) scores = q @ k^T (causal skip)
    gemm_f16<<<dim3(S / BM, S / BN, NH), 256>>>(
        qkv, qkv + NH * HD, scores,
        HD, QKV_DIM, QKV_DIM, S,
        HD, HD, 2, (long long)S * S, 1);

    // 6) causal softmax
    softmax_causal<<<dim3(S, NH), 256>>>(scores);

    // 7) o_h = P_h @ vt_h^T (K clamped causally)
    gemm_f16<<<dim3(S / BM, 1, NH), 256>>>(
        scores, vt, o,
        S, S, S, DIM,
        (long long)S * S, (long long)HD * S, 2, HD, 2);

    // 8) attn = o @ wo^T
    gemm_f16<<<dim3(S / BM, DIM / BN, 1), 256>>>(
        o, wo, tmp, DIM, DIM, DIM, DIM, 0, 0, 1, 0, 0);

    // 9) h2 = x + attn
    add_kernel<<<(S * DIM) / 256, 256>>>(x, tmp, h2, (long long)S * DIM);

    // 10) g = rmsnorm(h2)
    rmsnorm_kernel<<<S, 256>>>(h2, ffn_norm_w, h);

    // 11) x13 = g @ w13^T
    gemm_f16<<<dim3(S / BM, (2 * HID) / BN, 1), 256>>>(
        h, w13, x13, DIM, DIM, DIM, 2 * HID, 0, 0, 1, 0, 0);

    // 12) gate = silu(x1) * x3
    swiglu_kernel<<<(S * HID + 255) / 256, 256>>>(x13, gate);

    // 13) ffn = gate @ w2^T
    gemm_f16<<<dim3(S / BM, DIM / BN, 1), 256>>>(
        gate, w2, tmp, HID, HID, HID, DIM, 0, 0, 1, 0, 0);

    // 14) out = h2 + ffn
    add_kernel<<<(S * DIM) / 256, 256>>>(h2, tmp, out, (long long)S * DIM);
}

// round 6
// speedup vs baseline: 7.2814x; 1.3893x over previous
#include <cuda_runtime.h>
#include <cuda_fp16.h>
#include <math.h>
#include <stdint.h>

#define S 2048
#define DIM 2048
#define NH 16
#define NKV 8
#define HD 128
#define HID 5632
#define QKV_DIM ((NH + 2*NKV) * HD)   // 4096
#define VOFF ((NH + NKV) * HD)        // 3072
#define EPS 1e-5f

// ---------------- scratch ----------------
__device__ __align__(256) __half g_h16[(size_t)S * DIM];
__device__ __align__(256) __half g_qkv16[(size_t)S * QKV_DIM];
__device__ __align__(256) __half g_p16[(size_t)NH * S * S];
__device__ __align__(256) __half g_o16[(size_t)S * DIM];
__device__ __align__(256) __half g_x13_16[(size_t)S * 2 * HID];
__device__ __align__(256) __half g_gate16[(size_t)S * HID];
__device__ __align__(256) __half g_vt16[(size_t)NKV * HD * S];
__device__ __align__(256) __half g_wqkv16[(size_t)QKV_DIM * DIM];
__device__ __align__(256) __half g_wo16[(size_t)DIM * DIM];
__device__ __align__(256) __half g_w13_16[(size_t)2 * HID * DIM];
__device__ __align__(256) __half g_w2_16[(size_t)DIM * HID];
__device__ float g_scores[(size_t)NH * S * S];
__device__ float g_tmp[(size_t)S * DIM];
__device__ float g_h2[(size_t)S * DIM];

// ---------------- helpers ----------------
__device__ __forceinline__ uint32_t sm2u(const void* p) {
    uint32_t a;
    asm("{ .reg .u64 t; cvta.to.shared.u64 t, %1; cvt.u32.u64 %0, t; }" : "=r"(a) : "l"(p));
    return a;
}

// fp16 tile [128 rows][32 halves] = 8KB; row pairs share a 128B line, 8x16B
// segments XOR-swizzled. k granularity: 8 halves = 16B.
__device__ __forceinline__ uint32_t smoff(uint32_t m, uint32_t k) {
    return (m >> 1) * 128u
         + (((((m & 1u) << 2) | (k >> 3)) ^ ((m >> 1) & 7u)) << 4)
         + (k & 7u) * 2u;
}

__device__ __forceinline__ uint4 ldm4(uint32_t addr) {
    uint4 r;
    asm volatile("ldmatrix.sync.aligned.m8n8.x4.shared.b16 {%0,%1,%2,%3}, [%4];"
                 : "=r"(r.x), "=r"(r.y), "=r"(r.z), "=r"(r.w) : "r"(addr));
    return r;
}

__device__ __forceinline__ void mma_f16(float* c, const uint4& a, uint32_t b0, uint32_t b1) {
    asm volatile(
        "mma.sync.aligned.m16n8k16.row.col.f32.f16.f16.f32 "
        "{%0,%1,%2,%3}, {%4,%5,%6,%7}, {%8,%9}, {%0,%1,%2,%3};"
        : "+f"(c[0]), "+f"(c[1]), "+f"(c[2]), "+f"(c[3])
        : "r"(a.x), "r"(a.y), "r"(a.z), "r"(a.w), "r"(b0), "r"(b1));
}

__device__ __forceinline__ void cpasync16(uint32_t dst, const void* src) {
    asm volatile("cp.async.cg.shared.global [%0], [%1], 16;" :: "r"(dst), "l"(src) : "memory");
}
__device__ __forceinline__ void cpcommit() {
    asm volatile("cp.async.commit_group;" ::: "memory");
}
template<int N> __device__ __forceinline__ void cpwait() {
    asm volatile("cp.async.wait_group %0;" :: "n"(N) : "memory");
}

__device__ __forceinline__ void st2(float* p, float a, float b) {
    *reinterpret_cast<float2*>(p) = make_float2(a, b);
}
__device__ __forceinline__ void st2(__half* p, float a, float b) {
    *reinterpret_cast<__half2*>(p) = __floats2half2_rn(a, b);
}

// ---------------- fp16 cp.async NT GEMM ----------------
// C[M,N] = A[M,K] @ B[N,K]^T; A,B fp16 row-major; C fp32 or fp16.
// Tile 128x128x32, 8 warps (2x4 of 64x32), 4-stage cp.async pipeline.
// Pipeline invariant: exactly one commit_group per iteration (real or EMPTY),
// so before each cpwait<2> exactly 3 groups are pending and wait_group 2
// always forces completion of the group feeding this iteration's stage.
// causalMode: 0 none, 1 skip bn>bm (scores), 2 clamp K at bm+128 (PV).
#define BM 128
#define BN 128
#define BK 32
#define ATILE_B 8192
#define STAGE_B 16384
#define NSTAGE 4

template<typename OutT>
__global__ void __launch_bounds__(256, 2)
gemm_cp(const __half* __restrict__ A, const __half* __restrict__ B, OutT* __restrict__ C,
        int K, int lda, int ldb, int ldc,
        long long aBOff, long long bBOff, int bDiv, long long cBOff, int causalMode)
{
    int bm = blockIdx.x * BM;
    int bn = blockIdx.y * BN;
    if (causalMode == 1 && bn > bm) return;

    int z = blockIdx.z;
    A += (long long)z * aBOff;
    B += (long long)(z / bDiv) * bBOff;
    C += (long long)z * cBOff;

    extern __shared__ unsigned char smraw[];
    uint32_t smB = (sm2u(smraw) + 1023) & ~1023u;

    int tid  = threadIdx.x;
    int lane = tid & 31;
    int warp = tid >> 5;
    int wm = warp >> 2;
    int wn = warp & 3;

    int kmax = (causalMode == 2) ? (bm + BM) : K;
    int nCh  = kmax / BK;

    // producer: chunk idx c = tid (+256): row m = c>>2, k-chunk kc = (c&3)*8
    int m0  = tid >> 2;
    int kc0 = (tid & 3) * 8;
    const __half* Ag = A + (long long)bm * lda;
    const __half* Bg = B + (long long)bn * ldb;
    uint32_t so0 = smoff(m0, kc0);
    uint32_t so1 = smoff(m0 + 64, kc0);

    auto issue = [&](int c) {
        uint32_t aB = smB + (c & (NSTAGE - 1)) * STAGE_B;
        uint32_t bB = aB + ATILE_B;
        int k0 = c * BK + kc0;
        cpasync16(aB + so0, Ag + (long long)m0 * lda + k0);
        cpasync16(aB + so1, Ag + (long long)(m0 + 64) * lda + k0);
        cpasync16(bB + so0, Bg + (long long)m0 * ldb + k0);
        cpasync16(bB + so1, Bg + (long long)(m0 + 64) * ldb + k0);
        cpcommit();
    };

    // consumer ldmatrix base addresses (ks=0; ks=1 is XOR 32)
    uint32_t aAdr[4], bAdr[2];
    {
        int mi = lane >> 3;
        int ra = (lane & 7) + (mi & 1) * 8;
        int ka = (mi >> 1) * 8;
        #pragma unroll
        for (int g = 0; g < 4; ++g) aAdr[g] = smoff(wm * 64 + g * 16 + ra, ka);
        int rb = (lane & 7) + (mi >> 1) * 8;
        int kb = (mi & 1) * 8;
        #pragma unroll
        for (int g = 0; g < 2; ++g) bAdr[g] = smoff(wn * 32 + g * 16 + rb, kb);
    }

    float acc[4][4][4];
    #pragma unroll
    for (int a = 0; a < 4; ++a)
        #pragma unroll
        for (int b = 0; b < 4; ++b)
            #pragma unroll
            for (int c = 0; c < 4; ++c) acc[a][b][c] = 0.f;

    // prologue: commit exactly 3 groups (pad with empty groups if nCh < 3)
    #pragma unroll
    for (int c = 0; c < 3; ++c) {
        if (c < nCh) issue(c);
        else cpcommit();
    }

    for (int it = 0; it < nCh; ++it) {
        cpwait<2>();          // 3 pending -> forces group 'it' complete
        __syncthreads();
        if (it + 3 < nCh) issue(it + 3);
        else cpcommit();      // keep one-commit-per-iteration invariant

        uint32_t aB = smB + (it & (NSTAGE - 1)) * STAGE_B;
        uint32_t bB = aB + ATILE_B;

        #pragma unroll
        for (int ks = 0; ks < 2; ++ks) {
            uint32_t kx = ks ? 32u : 0u;
            uint4 av[4], bv[2];
            #pragma unroll
            for (int g = 0; g < 4; ++g) av[g] = ldm4(aB + (aAdr[g] ^ kx));
            #pragma unroll
            for (int g = 0; g < 2; ++g) bv[g] = ldm4(bB + (bAdr[g] ^ kx));
            #pragma unroll
            for (int mi = 0; mi < 4; ++mi) {
                #pragma unroll
                for (int nj = 0; nj < 4; ++nj) {
                    uint32_t b0 = (nj & 1) ? bv[nj >> 1].z : bv[nj >> 1].x;
                    uint32_t b1 = (nj & 1) ? bv[nj >> 1].w : bv[nj >> 1].y;
                    mma_f16(acc[mi][nj], av[mi], b0, b1);
                }
            }
        }
    }
    cpwait<0>();   // drain tail empty groups before block exits

    // epilogue
    int grp = lane >> 2;
    int tg  = lane & 3;
    #pragma unroll
    for (int mi = 0; mi < 4; ++mi) {
        long long r0 = bm + wm * 64 + mi * 16 + grp;
        #pragma unroll
        for (int nj = 0; nj < 4; ++nj) {
            int c0 = bn + wn * 32 + nj * 8 + tg * 2;
            st2(&C[r0 * ldc + c0],       acc[mi][nj][0], acc[mi][nj][1]);
            st2(&C[(r0 + 8) * ldc + c0], acc[mi][nj][2], acc[mi][nj][3]);
        }
    }
}

// ---------------- fp32 -> fp16 ----------------
__global__ void f2h_kernel(const float* __restrict__ in, __half* __restrict__ out, long long n)
{
    long long i = ((long long)blockIdx.x * 256 + threadIdx.x) * 4;
    if (i < n) {
        float4 v = *reinterpret_cast<const float4*>(in + i);
        *reinterpret_cast<__half2*>(out + i)     = __floats2half2_rn(v.x, v.y);
        *reinterpret_cast<__half2*>(out + i + 2) = __floats2half2_rn(v.z, v.w);
    }
}

// ---------------- V transpose (half -> half) ----------------
__global__ void transpose_v(const __half* __restrict__ qkv, __half* __restrict__ vt)
{
    __shared__ float t[32][33];
    int s0 = blockIdx.x * 32;
    int d0 = blockIdx.y * 32;
    int tx = threadIdx.x, ty = threadIdx.y;   // 32 x 8
    #pragma unroll
    for (int j = 0; j < 32; j += 8)
        t[ty + j][tx] = __half2float(qkv[(long long)(s0 + ty + j) * QKV_DIM + VOFF + d0 + tx]);
    __syncthreads();
    #pragma unroll
    for (int j = 0; j < 32; j += 8)
        vt[(long long)(d0 + ty + j) * S + s0 + tx] = __float2half_rn(t[tx][ty + j]);
}

// ---------------- norm / elementwise ----------------
__global__ void rmsnorm_h(const float* __restrict__ x, const float* __restrict__ w,
                          __half* __restrict__ out)
{
    int row = blockIdx.x;
    const float* xr = x + (long long)row * DIM;
    __shared__ float red[256];
    int t = threadIdx.x;
    float s = 0.f;
    for (int i = t; i < DIM; i += 256) { float v = xr[i]; s += v * v; }
    red[t] = s; __syncthreads();
    for (int o = 128; o > 0; o >>= 1) { if (t < o) red[t] += red[t + o]; __syncthreads(); }
    float inv = rsqrtf(red[0] / (float)DIM + EPS);
    __half* orow = out + (long long)row * DIM;
    for (int i = t; i < DIM; i += 256) orow[i] = __float2half_rn(xr[i] * inv * w[i]);
}

__global__ void qknorm_rope_h(__half* __restrict__ qkv,
                              const float* __restrict__ qn_w, const float* __restrict__ qn_b,
                              const float* __restrict__ kn_w, const float* __restrict__ kn_b,
                              const float* __restrict__ fcos, const float* __restrict__ fsin)
{
    int s = blockIdx.x;
    int h = blockIdx.y;
    bool isq = (h < NH);
    int col = isq ? h * HD : NH * HD + (h - NH) * HD;
    __half* p = qkv + (long long)s * QKV_DIM + col;
    const float* w = isq ? qn_w : kn_w;
    const float* b = isq ? qn_b : kn_b;

    int t = threadIdx.x;
    float v = __half2float(p[t]);

    __shared__ float sm[4], sv[4];
    float m = v;
    #pragma unroll
    for (int o = 16; o; o >>= 1) m += __shfl_xor_sync(0xffffffffu, m, o);
    if ((t & 31) == 0) sm[t >> 5] = m;
    __syncthreads();
    float mean = (sm[0] + sm[1] + sm[2] + sm[3]) * (1.f / HD);
    float d = v - mean;
    float vv = d * d;
    #pragma unroll
    for (int o = 16; o; o >>= 1) vv += __shfl_xor_sync(0xffffffffu, vv, o);
    if ((t & 31) == 0) sv[t >> 5] = vv;
    __syncthreads();
    float var = (sv[0] + sv[1] + sv[2] + sv[3]) * (1.f / HD);
    float n = d * rsqrtf(var + EPS) * w[t] + b[t];

    __shared__ float sh[HD];
    sh[t] = n; __syncthreads();

    float c  = fcos[(long long)s * (HD / 2) + (t >> 1)];
    float si = fsin[(long long)s * (HD / 2) + (t >> 1)];
    float x0 = sh[t & ~1];
    float x1 = sh[t | 1];
    float r  = ((t & 1) == 0) ? (x0 * c - x1 * si) : (x0 * si + x1 * c);
    p[t] = __float2half_rn(r);
}

// causal softmax: fp32 scores in (scratch, rewritten), fp16 probs out.
__global__ void softmax_causal(float* __restrict__ scores, __half* __restrict__ p)
{
    int i = blockIdx.x;
    int h = blockIdx.y;
    float* row = scores + ((long long)h * S + i) * S;
    __half* prow = p + ((long long)h * S + i) * S;
    const float sc = 0.08838834764831845f;   // 1/sqrt(128)
    int lim = ((i >> 7) + 1) << 7;

    __shared__ float red[256];
    int t = threadIdx.x;

    float mx = -1e30f;
    for (int j = t; j <= i; j += 256) mx = fmaxf(mx, row[j] * sc);
    red[t] = mx; __syncthreads();
    for (int o = 128; o > 0; o >>= 1) { if (t < o) red[t] = fmaxf(red[t], red[t + o]); __syncthreads(); }
    mx = red[0]; __syncthreads();

    float sum = 0.f;
    for (int j = t; j <= i; j += 256) {
        float v = expf(row[j] * sc - mx);
        row[j] = v;
        sum += v;
    }
    red[t] = sum; __syncthreads();
    for (int o = 128; o > 0; o >>= 1) { if (t < o) red[t] += red[t + o]; __syncthreads(); }
    float inv = 1.f / red[0];
    for (int j = t; j < lim; j += 256)
        prow[j] = __float2half_rn((j <= i) ? row[j] * inv : 0.f);
}

__global__ void add_kernel(const float* __restrict__ a, const float* __restrict__ b,
                           float* __restrict__ out, long long n)
{
    long long i = (long long)blockIdx.x * 256 + threadIdx.x;
    if (i < n) out[i] = a[i] + b[i];
}

__global__ void swiglu_h(const __half* __restrict__ x13, __half* __restrict__ gate)
{
    unsigned idx = blockIdx.x * 256u + threadIdx.x;
    if (idx >= (unsigned)(S * HID)) return;
    unsigned s = idx / HID;
    unsigned j = idx - s * HID;
    float a = __half2float(x13[(size_t)s * (2 * HID) + j]);
    float b = __half2float(x13[(size_t)s * (2 * HID) + HID + j]);
    float sig = 1.f / (1.f + expf(-a));
    gate[idx] = __float2half_rn(a * sig * b);
}

// ---------------- launcher ----------------
extern "C" void kernel_launch(void* const* d_in, const int* in_sizes, int n_in,
                              void* d_out, int out_size)
{
    const float* x           = (const float*)d_in[0];
    const float* fcos        = (const float*)d_in[1];
    const float* fsin        = (const float*)d_in[2];
    const float* wqkv        = (const float*)d_in[4];
    const float* wo          = (const float*)d_in[5];
    const float* qn_w        = (const float*)d_in[6];
    const float* qn_b        = (const float*)d_in[7];
    const float* kn_w        = (const float*)d_in[8];
    const float* kn_b        = (const float*)d_in[9];
    const float* attn_norm_w = (const float*)d_in[10];
    const float* ffn_norm_w  = (const float*)d_in[11];
    const float* w13         = (const float*)d_in[12];
    const float* w2          = (const float*)d_in[13];
    float* out = (float*)d_out;

    __half *h16, *qkv16, *p16, *o16, *x13_16, *gate16, *vt16;
    __half *wqkv16, *wo16, *w13_16, *w2_16;
    float *scores, *tmp, *h2;
    cudaGetSymbolAddress((void**)&h16,     g_h16);
    cudaGetSymbolAddress((void**)&qkv16,   g_qkv16);
    cudaGetSymbolAddress((void**)&p16,     g_p16);
    cudaGetSymbolAddress((void**)&o16,     g_o16);
    cudaGetSymbolAddress((void**)&x13_16,  g_x13_16);
    cudaGetSymbolAddress((void**)&gate16,  g_gate16);
    cudaGetSymbolAddress((void**)&vt16,    g_vt16);
    cudaGetSymbolAddress((void**)&wqkv16,  g_wqkv16);
    cudaGetSymbolAddress((void**)&wo16,    g_wo16);
    cudaGetSymbolAddress((void**)&w13_16,  g_w13_16);
    cudaGetSymbolAddress((void**)&w2_16,   g_w2_16);
    cudaGetSymbolAddress((void**)&scores,  g_scores);
    cudaGetSymbolAddress((void**)&tmp,     g_tmp);
    cudaGetSymbolAddress((void**)&h2,      g_h2);

    const int SMEM = NSTAGE * STAGE_B + 1024;   // 65 KB + align pad
    cudaFuncSetAttribute(gemm_cp<float>,  cudaFuncAttributeMaxDynamicSharedMemorySize, SMEM);
    cudaFuncSetAttribute(gemm_cp<__half>, cudaFuncAttributeMaxDynamicSharedMemorySize, SMEM);

    // 0) weights -> fp16
    f2h_kernel<<<(QKV_DIM * (long long)DIM) / 1024, 256>>>(wqkv, wqkv16, (long long)QKV_DIM * DIM);
    f2h_kernel<<<((long long)DIM * DIM) / 1024, 256>>>(wo, wo16, (long long)DIM * DIM);
    f2h_kernel<<<(2LL * HID * DIM) / 1024, 256>>>(w13, w13_16, 2LL * HID * DIM);
    f2h_kernel<<<((long long)DIM * HID) / 1024, 256>>>(w2, w2_16, (long long)DIM * HID);

    // 1) h16 = rmsnorm(x)
    rmsnorm_h<<<S, 256>>>(x, attn_norm_w, h16);

    // 2) qkv16 = h16 @ wqkv^T
    gemm_cp<__half><<<dim3(S / BM, QKV_DIM / BN, 1), 256, SMEM>>>(
        h16, wqkv16, qkv16, DIM, DIM, DIM, QKV_DIM, 0, 0, 1, 0, 0);

    // 3) q/k layernorm + rope (in place, fp16)
    qknorm_rope_h<<<dim3(S, NH + NKV), HD>>>(qkv16, qn_w, qn_b, kn_w, kn_b, fcos, fsin);

    // 4) vt16 = V^T
    transpose_v<<<dim3(S / 32, (NKV * HD) / 32), dim3(32, 8)>>>(qkv16, vt16);

    // 5) scores = q @ k^T (fp32 out, causal skip)
    gemm_cp<float><<<dim3(S / BM, S / BN, NH), 256, SMEM>>>(
        qkv16, qkv16 + NH * HD, scores,
        HD, QKV_DIM, QKV_DIM, S,
        HD, HD, 2, (long long)S * S, 1);

    // 6) causal softmax -> fp16 probs
    softmax_causal<<<dim3(S, NH), 256>>>(scores, p16);

    // 7) o16 = P @ V (K clamped causally)
    gemm_cp<__half><<<dim3(S / BM, 1, NH), 256, SMEM>>>(
        p16, vt16, o16,
        S, S, S, DIM,
        (long long)S * S, (long long)HD * S, 2, HD, 2);

    // 8) tmp = o @ wo^T
    gemm_cp<float><<<dim3(S / BM, DIM / BN, 1), 256, SMEM>>>(
        o16, wo16, tmp, DIM, DIM, DIM, DIM, 0, 0, 1, 0, 0);

    // 9) h2 = x + tmp
    add_kernel<<<(S * DIM) / 256, 256>>>(x, tmp, h2, (long long)S * DIM);

    // 10) h16 = rmsnorm(h2)
    rmsnorm_h<<<S, 256>>>(h2, ffn_norm_w, h16);

    // 11) x13_16 = g @ w13^T
    gemm_cp<__half><<<dim3(S / BM, (2 * HID) / BN, 1), 256, SMEM>>>(
        h16, w13_16, x13_16, DIM, DIM, DIM, 2 * HID, 0, 0, 1, 0, 0);

    // 12) gate16 = silu(x1) * x3
    swiglu_h<<<(S * HID + 255) / 256, 256>>>(x13_16, gate16);

    // 13) tmp = gate @ w2^T
    gemm_cp<float><<<dim3(S / BM, DIM / BN, 1), 256, SMEM>>>(
        gate16, w2_16, tmp, HID, HID, HID, DIM, 0, 0, 1, 0, 0);

    // 14) out = h2 + tmp
    add_kernel<<<(S * DIM) / 256, 256>>>(h2, tmp, out, (long long)S * DIM);
}

// round 7
// speedup vs baseline: 8.1993x; 1.1261x over previous
#include <cuda_runtime.h>
#include <cuda_fp16.h>
#include <math.h>
#include <stdint.h>

#define S 2048
#define DIM 2048
#define NH 16
#define NKV 8
#define HD 128
#define HID 5632
#define QKV_DIM ((NH + 2*NKV) * HD)   // 4096
#define VOFF ((NH + NKV) * HD)        // 3072
#define EPS 1e-5f

// ---------------- scratch ----------------
__device__ __align__(256) __half g_h16[(size_t)S * DIM];
__device__ __align__(256) __half g_qkv16[(size_t)S * QKV_DIM];
__device__ __align__(256) __half g_o16[(size_t)S * DIM];
__device__ __align__(256) __half g_x13_16[(size_t)S * 2 * HID];
__device__ __align__(256) __half g_gate16[(size_t)S * HID];
__device__ __align__(256) __half g_vt16[(size_t)NKV * HD * S];
__device__ __align__(256) __half g_wqkv16[(size_t)QKV_DIM * DIM];
__device__ __align__(256) __half g_wo16[(size_t)DIM * DIM];
__device__ __align__(256) __half g_w13_16[(size_t)2 * HID * DIM];
__device__ __align__(256) __half g_w2_16[(size_t)DIM * HID];
__device__ float g_h2[(size_t)S * DIM];

// ---------------- helpers ----------------
__device__ __forceinline__ uint32_t sm2u(const void* p) {
    uint32_t a;
    asm("{ .reg .u64 t; cvta.to.shared.u64 t, %1; cvt.u32.u64 %0, t; }" : "=r"(a) : "l"(p));
    return a;
}

// fp16 tile [128 rows][32 halves] = 8KB (GEMM operand staging)
__device__ __forceinline__ uint32_t smoff(uint32_t m, uint32_t k) {
    return (m >> 1) * 128u
         + (((((m & 1u) << 2) | (k >> 3)) ^ ((m >> 1) & 7u)) << 4)
         + (k & 7u) * 2u;
}

// fp16 tile [128 rows][128 halves] = 32KB (flash attention tiles)
// row pitch 256B = 16 chunks of 16B, chunk index XOR-swizzled by row&7.
__device__ __forceinline__ uint32_t smoff256(uint32_t r, uint32_t chunk) {
    return r * 256u + (((chunk ^ (r & 7u)) & 15u) << 4);
}

__device__ __forceinline__ uint4 ldm4(uint32_t addr) {
    uint4 r;
    asm volatile("ldmatrix.sync.aligned.m8n8.x4.shared.b16 {%0,%1,%2,%3}, [%4];"
                 : "=r"(r.x), "=r"(r.y), "=r"(r.z), "=r"(r.w) : "r"(addr));
    return r;
}

__device__ __forceinline__ void mma_f16(float* c, const uint4& a, uint32_t b0, uint32_t b1) {
    asm volatile(
        "mma.sync.aligned.m16n8k16.row.col.f32.f16.f16.f32 "
        "{%0,%1,%2,%3}, {%4,%5,%6,%7}, {%8,%9}, {%0,%1,%2,%3};"
        : "+f"(c[0]), "+f"(c[1]), "+f"(c[2]), "+f"(c[3])
        : "r"(a.x), "r"(a.y), "r"(a.z), "r"(a.w), "r"(b0), "r"(b1));
}

__device__ __forceinline__ void cpasync16(uint32_t dst, const void* src) {
    asm volatile("cp.async.cg.shared.global [%0], [%1], 16;" :: "r"(dst), "l"(src) : "memory");
}
__device__ __forceinline__ void cpcommit() {
    asm volatile("cp.async.commit_group;" ::: "memory");
}
template<int N> __device__ __forceinline__ void cpwait() {
    asm volatile("cp.async.wait_group %0;" :: "n"(N) : "memory");
}

__device__ __forceinline__ uint32_t h2u(float a, float b) {
    __half2 h = __floats2half2_rn(a, b);
    return *reinterpret_cast<uint32_t*>(&h);
}
__device__ __forceinline__ void st2(float* p, float a, float b) {
    *reinterpret_cast<float2*>(p) = make_float2(a, b);
}
__device__ __forceinline__ void st2(__half* p, float a, float b) {
    *reinterpret_cast<__half2*>(p) = __floats2half2_rn(a, b);
}

// ---------------- fp16 cp.async NT GEMM ----------------
// C[M,N] = A[M,K] @ B[N,K]^T (+ optional fp32 residual); 128x128x32 tile,
// 8 warps, 4-stage cp.async pipeline with one-commit-per-iteration invariant.
#define BM 128
#define BN 128
#define BK 32
#define ATILE_B 8192
#define STAGE_B 16384
#define NSTAGE 4

template<typename OutT>
__global__ void __launch_bounds__(256, 2)
gemm_cp(const __half* __restrict__ A, const __half* __restrict__ B, OutT* __restrict__ C,
        int K, int lda, int ldb, int ldc, const float* __restrict__ res)
{
    int bm = blockIdx.x * BM;
    int bn = blockIdx.y * BN;

    extern __shared__ unsigned char smraw[];
    uint32_t smB = (sm2u(smraw) + 1023) & ~1023u;

    int tid  = threadIdx.x;
    int lane = tid & 31;
    int warp = tid >> 5;
    int wm = warp >> 2;
    int wn = warp & 3;

    int nCh = K / BK;

    int m0  = tid >> 2;
    int kc0 = (tid & 3) * 8;
    const __half* Ag = A + (long long)bm * lda;
    const __half* Bg = B + (long long)bn * ldb;
    uint32_t so0 = smoff(m0, kc0);
    uint32_t so1 = smoff(m0 + 64, kc0);

    auto issue = [&](int c) {
        uint32_t aB = smB + (c & (NSTAGE - 1)) * STAGE_B;
        uint32_t bB = aB + ATILE_B;
        int k0 = c * BK + kc0;
        cpasync16(aB + so0, Ag + (long long)m0 * lda + k0);
        cpasync16(aB + so1, Ag + (long long)(m0 + 64) * lda + k0);
        cpasync16(bB + so0, Bg + (long long)m0 * ldb + k0);
        cpasync16(bB + so1, Bg + (long long)(m0 + 64) * ldb + k0);
        cpcommit();
    };

    uint32_t aAdr[4], bAdr[2];
    {
        int mi = lane >> 3;
        int ra = (lane & 7) + (mi & 1) * 8;
        int ka = (mi >> 1) * 8;
        #pragma unroll
        for (int g = 0; g < 4; ++g) aAdr[g] = smoff(wm * 64 + g * 16 + ra, ka);
        int rb = (lane & 7) + (mi >> 1) * 8;
        int kb = (mi & 1) * 8;
        #pragma unroll
        for (int g = 0; g < 2; ++g) bAdr[g] = smoff(wn * 32 + g * 16 + rb, kb);
    }

    float acc[4][4][4];
    #pragma unroll
    for (int a = 0; a < 4; ++a)
        #pragma unroll
        for (int b = 0; b < 4; ++b)
            #pragma unroll
            for (int c = 0; c < 4; ++c) acc[a][b][c] = 0.f;

    #pragma unroll
    for (int c = 0; c < 3; ++c) {
        if (c < nCh) issue(c);
        else cpcommit();
    }

    for (int it = 0; it < nCh; ++it) {
        cpwait<2>();
        __syncthreads();
        if (it + 3 < nCh) issue(it + 3);
        else cpcommit();

        uint32_t aB = smB + (it & (NSTAGE - 1)) * STAGE_B;
        uint32_t bB = aB + ATILE_B;

        #pragma unroll
        for (int ks = 0; ks < 2; ++ks) {
            uint32_t kx = ks ? 32u : 0u;
            uint4 av[4], bv[2];
            #pragma unroll
            for (int g = 0; g < 4; ++g) av[g] = ldm4(aB + (aAdr[g] ^ kx));
            #pragma unroll
            for (int g = 0; g < 2; ++g) bv[g] = ldm4(bB + (bAdr[g] ^ kx));
            #pragma unroll
            for (int mi = 0; mi < 4; ++mi) {
                #pragma unroll
                for (int nj = 0; nj < 4; ++nj) {
                    uint32_t b0 = (nj & 1) ? bv[nj >> 1].z : bv[nj >> 1].x;
                    uint32_t b1 = (nj & 1) ? bv[nj >> 1].w : bv[nj >> 1].y;
                    mma_f16(acc[mi][nj], av[mi], b0, b1);
                }
            }
        }
    }
    cpwait<0>();

    int grp = lane >> 2;
    int tg  = lane & 3;
    #pragma unroll
    for (int mi = 0; mi < 4; ++mi) {
        long long r0 = bm + wm * 64 + mi * 16 + grp;
        #pragma unroll
        for (int nj = 0; nj < 4; ++nj) {
            int c0 = bn + wn * 32 + nj * 8 + tg * 2;
            float v0 = acc[mi][nj][0], v1 = acc[mi][nj][1];
            float v2 = acc[mi][nj][2], v3 = acc[mi][nj][3];
            if (res) {
                float2 r01 = *reinterpret_cast<const float2*>(&res[r0 * ldc + c0]);
                float2 r23 = *reinterpret_cast<const float2*>(&res[(r0 + 8) * ldc + c0]);
                v0 += r01.x; v1 += r01.y; v2 += r23.x; v3 += r23.y;
            }
            st2(&C[r0 * ldc + c0],       v0, v1);
            st2(&C[(r0 + 8) * ldc + c0], v2, v3);
        }
    }
}

// ---------------- fused flash attention ----------------
// grid (16 qb, 16 heads), 256 threads. Each warp owns 16 query rows.
// Q in registers; K/V 128-key blocks double-buffered via cp.async.
// Online softmax in registers; P passed fragment-to-fragment to PV mma.
__global__ void __launch_bounds__(256)
flash_attn(const __half* __restrict__ qkv, const __half* __restrict__ vt,
           __half* __restrict__ o)
{
    int qb = 15 - blockIdx.x;          // heavy blocks first
    int h  = blockIdx.y;
    int nb = qb + 1;

    extern __shared__ unsigned char smraw[];
    uint32_t smQ = (sm2u(smraw) + 255) & ~255u;
    uint32_t smK = smQ + 32768;
    uint32_t smV = smK + 2 * 32768;

    int tid  = threadIdx.x;
    int lane = tid & 31;
    int warp = tid >> 5;
    int wrow = warp * 16;
    int grp  = lane >> 2;
    int tg   = lane & 3;

    const __half* Qg = qkv + (size_t)(qb * 128) * QKV_DIM + h * HD;
    const __half* Kg = qkv + NH * HD + (h >> 1) * HD;            // [key][dim]
    const __half* Vg = vt + (size_t)((h >> 1) * HD) * S;         // [dim][key]

    int prow = tid >> 1;
    int pc0  = (tid & 1) * 8;

    auto issueQ = [&]() {
        #pragma unroll
        for (int i = 0; i < 8; ++i) {
            int ch = pc0 + i;
            cpasync16(smQ + smoff256(prow, ch), Qg + (size_t)prow * QKV_DIM + ch * 8);
        }
    };
    auto issueKV = [&](int b) {
        uint32_t kB = smK + (b & 1) * 32768;
        uint32_t vB = smV + (b & 1) * 32768;
        #pragma unroll
        for (int i = 0; i < 8; ++i) {
            int ch = pc0 + i;
            uint32_t off = smoff256(prow, ch);
            cpasync16(kB + off, Kg + (size_t)(b * 128 + prow) * QKV_DIM + ch * 8);
            cpasync16(vB + off, Vg + (size_t)prow * S + b * 128 + ch * 8);
        }
    };

    issueQ();
    issueKV(0);
    cpcommit();

    // fragment lane mapping
    int mi   = lane >> 3;
    int frow = (lane & 7) + (mi & 1) * 8;     // A row within 16
    int fkc  = (mi >> 1);                     // A k chunk (0/1) within 16
    int brow = (lane & 7) + (mi >> 1) * 8;    // B n-row within 16
    int bkc  = (mi & 1);                      // B k chunk (0/1) within 16

    float m0 = -1e30f, m1 = -1e30f, l0 = 0.f, l1 = 0.f;
    float O[16][4];
    #pragma unroll
    for (int j = 0; j < 16; ++j)
        #pragma unroll
        for (int c = 0; c < 4; ++c) O[j][c] = 0.f;

    uint4 qf[8];
    const float CS = 0.1275447941f;   // (1/sqrt(128)) * log2(e)

    for (int b = 0; b < nb; ++b) {
        cpwait<0>();
        __syncthreads();

        if (b == 0) {
            #pragma unroll
            for (int ks = 0; ks < 8; ++ks)
                qf[ks] = ldm4(smQ + smoff256(wrow + frow, ks * 2 + fkc));
        }
        if (b + 1 < nb) { issueKV(b + 1); cpcommit(); }

        uint32_t kB = smK + (b & 1) * 32768;
        uint32_t vB = smV + (b & 1) * 32768;

        // ---- S = Q @ K^T  (16 x 128 per warp) ----
        float Sv[16][4];
        #pragma unroll
        for (int j = 0; j < 16; ++j)
            #pragma unroll
            for (int c = 0; c < 4; ++c) Sv[j][c] = 0.f;

        #pragma unroll
        for (int ks = 0; ks < 8; ++ks) {
            #pragma unroll
            for (int g = 0; g < 8; ++g) {
                uint4 bv = ldm4(kB + smoff256(g * 16 + brow, ks * 2 + bkc));
                mma_f16(Sv[2 * g],     qf[ks], bv.x, bv.y);
                mma_f16(Sv[2 * g + 1], qf[ks], bv.z, bv.w);
            }
        }

        // ---- causal mask (diagonal block only) ----
        if (b == qb) {
            int r0 = wrow + grp;
            #pragma unroll
            for (int j = 0; j < 16; ++j) {
                int c0 = j * 8 + tg * 2;
                if (c0     > r0)     Sv[j][0] = -1e30f;
                if (c0 + 1 > r0)     Sv[j][1] = -1e30f;
                if (c0     > r0 + 8) Sv[j][2] = -1e30f;
                if (c0 + 1 > r0 + 8) Sv[j][3] = -1e30f;
            }
        }

        // ---- online softmax ----
        float bm0 = -1e30f, bm1 = -1e30f;
        #pragma unroll
        for (int j = 0; j < 16; ++j) {
            bm0 = fmaxf(bm0, fmaxf(Sv[j][0], Sv[j][1]));
            bm1 = fmaxf(bm1, fmaxf(Sv[j][2], Sv[j][3]));
        }
        bm0 = fmaxf(bm0, __shfl_xor_sync(0xffffffffu, bm0, 1));
        bm0 = fmaxf(bm0, __shfl_xor_sync(0xffffffffu, bm0, 2));
        bm1 = fmaxf(bm1, __shfl_xor_sync(0xffffffffu, bm1, 1));
        bm1 = fmaxf(bm1, __shfl_xor_sync(0xffffffffu, bm1, 2));

        float nm0 = fmaxf(m0, bm0), nm1 = fmaxf(m1, bm1);
        float sc0 = exp2f((m0 - nm0) * CS), sc1 = exp2f((m1 - nm1) * CS);
        m0 = nm0; m1 = nm1;

        float rs0 = 0.f, rs1 = 0.f;
        #pragma unroll
        for (int j = 0; j < 16; ++j) {
            Sv[j][0] = exp2f((Sv[j][0] - nm0) * CS); rs0 += Sv[j][0];
            Sv[j][1] = exp2f((Sv[j][1] - nm0) * CS); rs0 += Sv[j][1];
            Sv[j][2] = exp2f((Sv[j][2] - nm1) * CS); rs1 += Sv[j][2];
            Sv[j][3] = exp2f((Sv[j][3] - nm1) * CS); rs1 += Sv[j][3];
        }
        l0 = l0 * sc0 + rs0;   // per-thread partial; quad-reduced at the end
        l1 = l1 * sc1 + rs1;

        #pragma unroll
        for (int j = 0; j < 16; ++j) {
            O[j][0] *= sc0; O[j][1] *= sc0;
            O[j][2] *= sc1; O[j][3] *= sc1;
        }

        // ---- O += P @ V ----
        #pragma unroll
        for (int ks = 0; ks < 8; ++ks) {
            uint4 pa;
            pa.x = h2u(Sv[2 * ks][0],     Sv[2 * ks][1]);
            pa.y = h2u(Sv[2 * ks][2],     Sv[2 * ks][3]);
            pa.z = h2u(Sv[2 * ks + 1][0], Sv[2 * ks + 1][1]);
            pa.w = h2u(Sv[2 * ks + 1][2], Sv[2 * ks + 1][3]);
            #pragma unroll
            for (int g = 0; g < 8; ++g) {
                uint4 bv = ldm4(vB + smoff256(g * 16 + brow, ks * 2 + bkc));
                mma_f16(O[2 * g],     pa, bv.x, bv.y);
                mma_f16(O[2 * g + 1], pa, bv.z, bv.w);
            }
        }
    }

    // ---- normalize + write ----
    l0 += __shfl_xor_sync(0xffffffffu, l0, 1);
    l0 += __shfl_xor_sync(0xffffffffu, l0, 2);
    l1 += __shfl_xor_sync(0xffffffffu, l1, 1);
    l1 += __shfl_xor_sync(0xffffffffu, l1, 2);
    float inv0 = 1.f / l0, inv1 = 1.f / l1;

    __half* o0 = o + (size_t)(qb * 128 + wrow + grp) * DIM + h * HD;
    __half* o1 = o0 + 8 * DIM;
    #pragma unroll
    for (int j = 0; j < 16; ++j) {
        int c0 = j * 8 + tg * 2;
        st2(o0 + c0, O[j][0] * inv0, O[j][1] * inv0);
        st2(o1 + c0, O[j][2] * inv1, O[j][3] * inv1);
    }
}

// ---------------- fp32 -> fp16 ----------------
__global__ void f2h_kernel(const float* __restrict__ in, __half* __restrict__ out, long long n)
{
    long long i = ((long long)blockIdx.x * 256 + threadIdx.x) * 4;
    if (i < n) {
        float4 v = *reinterpret_cast<const float4*>(in + i);
        *reinterpret_cast<__half2*>(out + i)     = __floats2half2_rn(v.x, v.y);
        *reinterpret_cast<__half2*>(out + i + 2) = __floats2half2_rn(v.z, v.w);
    }
}

// ---------------- V transpose (half -> half) ----------------
__global__ void transpose_v(const __half* __restrict__ qkv, __half* __restrict__ vt)
{
    __shared__ float t[32][33];
    int s0 = blockIdx.x * 32;
    int d0 = blockIdx.y * 32;
    int tx = threadIdx.x, ty = threadIdx.y;
    #pragma unroll
    for (int j = 0; j < 32; j += 8)
        t[ty + j][tx] = __half2float(qkv[(long long)(s0 + ty + j) * QKV_DIM + VOFF + d0 + tx]);
    __syncthreads();
    #pragma unroll
    for (int j = 0; j < 32; j += 8)
        vt[(long long)(d0 + ty + j) * S + s0 + tx] = __float2half_rn(t[tx][ty + j]);
}

// ---------------- norm / elementwise ----------------
__global__ void rmsnorm_h(const float* __restrict__ x, const float* __restrict__ w,
                          __half* __restrict__ out)
{
    int row = blockIdx.x;
    const float* xr = x + (long long)row * DIM;
    __shared__ float red[256];
    int t = threadIdx.x;
    float s = 0.f;
    for (int i = t; i < DIM; i += 256) { float v = xr[i]; s += v * v; }
    red[t] = s; __syncthreads();
    for (int o = 128; o > 0; o >>= 1) { if (t < o) red[t] += red[t + o]; __syncthreads(); }
    float inv = rsqrtf(red[0] / (float)DIM + EPS);
    __half* orow = out + (long long)row * DIM;
    for (int i = t; i < DIM; i += 256) orow[i] = __float2half_rn(xr[i] * inv * w[i]);
}

__global__ void qknorm_rope_h(__half* __restrict__ qkv,
                              const float* __restrict__ qn_w, const float* __restrict__ qn_b,
                              const float* __restrict__ kn_w, const float* __restrict__ kn_b,
                              const float* __restrict__ fcos, const float* __restrict__ fsin)
{
    int s = blockIdx.x;
    int h = blockIdx.y;
    bool isq = (h < NH);
    int col = isq ? h * HD : NH * HD + (h - NH) * HD;
    __half* p = qkv + (long long)s * QKV_DIM + col;
    const float* w = isq ? qn_w : kn_w;
    const float* b = isq ? qn_b : kn_b;

    int t = threadIdx.x;
    float v = __half2float(p[t]);

    __shared__ float sm[4], sv[4];
    float m = v;
    #pragma unroll
    for (int o = 16; o; o >>= 1) m += __shfl_xor_sync(0xffffffffu, m, o);
    if ((t & 31) == 0) sm[t >> 5] = m;
    __syncthreads();
    float mean = (sm[0] + sm[1] + sm[2] + sm[3]) * (1.f / HD);
    float d = v - mean;
    float vv = d * d;
    #pragma unroll
    for (int o = 16; o; o >>= 1) vv += __shfl_xor_sync(0xffffffffu, vv, o);
    if ((t & 31) == 0) sv[t >> 5] = vv;
    __syncthreads();
    float var = (sv[0] + sv[1] + sv[2] + sv[3]) * (1.f / HD);
    float n = d * rsqrtf(var + EPS) * w[t] + b[t];

    __shared__ float sh[HD];
    sh[t] = n; __syncthreads();

    float c  = fcos[(long long)s * (HD / 2) + (t >> 1)];
    float si = fsin[(long long)s * (HD / 2) + (t >> 1)];
    float x0 = sh[t & ~1];
    float x1 = sh[t | 1];
    float r  = ((t & 1) == 0) ? (x0 * c - x1 * si) : (x0 * si + x1 * c);
    p[t] = __float2half_rn(r);
}

__global__ void swiglu_h(const __half* __restrict__ x13, __half* __restrict__ gate)
{
    unsigned idx = blockIdx.x * 256u + threadIdx.x;
    if (idx >= (unsigned)(S * HID)) return;
    unsigned s = idx / HID;
    unsigned j = idx - s * HID;
    float a = __half2float(x13[(size_t)s * (2 * HID) + j]);
    float b = __half2float(x13[(size_t)s * (2 * HID) + HID + j]);
    float sig = 1.f / (1.f + expf(-a));
    gate[idx] = __float2half_rn(a * sig * b);
}

// ---------------- launcher ----------------
extern "C" void kernel_launch(void* const* d_in, const int* in_sizes, int n_in,
                              void* d_out, int out_size)
{
    const float* x           = (const float*)d_in[0];
    const float* fcos        = (const float*)d_in[1];
    const float* fsin        = (const float*)d_in[2];
    const float* wqkv        = (const float*)d_in[4];
    const float* wo          = (const float*)d_in[5];
    const float* qn_w        = (const float*)d_in[6];
    const float* qn_b        = (const float*)d_in[7];
    const float* kn_w        = (const float*)d_in[8];
    const float* kn_b        = (const float*)d_in[9];
    const float* attn_norm_w = (const float*)d_in[10];
    const float* ffn_norm_w  = (const float*)d_in[11];
    const float* w13         = (const float*)d_in[12];
    const float* w2          = (const float*)d_in[13];
    float* out = (float*)d_out;

    __half *h16, *qkv16, *o16, *x13_16, *gate16, *vt16;
    __half *wqkv16, *wo16, *w13_16, *w2_16;
    float *h2;
    cudaGetSymbolAddress((void**)&h16,     g_h16);
    cudaGetSymbolAddress((void**)&qkv16,   g_qkv16);
    cudaGetSymbolAddress((void**)&o16,     g_o16);
    cudaGetSymbolAddress((void**)&x13_16,  g_x13_16);
    cudaGetSymbolAddress((void**)&gate16,  g_gate16);
    cudaGetSymbolAddress((void**)&vt16,    g_vt16);
    cudaGetSymbolAddress((void**)&wqkv16,  g_wqkv16);
    cudaGetSymbolAddress((void**)&wo16,    g_wo16);
    cudaGetSymbolAddress((void**)&w13_16,  g_w13_16);
    cudaGetSymbolAddress((void**)&w2_16,   g_w2_16);
    cudaGetSymbolAddress((void**)&h2,      g_h2);

    const int SMEM = NSTAGE * STAGE_B + 1024;          // 65 KB + pad
    const int FSMEM = 5 * 32768 + 256;                 // 160 KB + pad
    cudaFuncSetAttribute(gemm_cp<float>,  cudaFuncAttributeMaxDynamicSharedMemorySize, SMEM);
    cudaFuncSetAttribute(gemm_cp<__half>, cudaFuncAttributeMaxDynamicSharedMemorySize, SMEM);
    cudaFuncSetAttribute(flash_attn,      cudaFuncAttributeMaxDynamicSharedMemorySize, FSMEM);

    // 0) weights -> fp16
    f2h_kernel<<<(QKV_DIM * (long long)DIM) / 1024, 256>>>(wqkv, wqkv16, (long long)QKV_DIM * DIM);
    f2h_kernel<<<((long long)DIM * DIM) / 1024, 256>>>(wo, wo16, (long long)DIM * DIM);
    f2h_kernel<<<(2LL * HID * DIM) / 1024, 256>>>(w13, w13_16, 2LL * HID * DIM);
    f2h_kernel<<<((long long)DIM * HID) / 1024, 256>>>(w2, w2_16, (long long)DIM * HID);

    // 1) h16 = rmsnorm(x)
    rmsnorm_h<<<S, 256>>>(x, attn_norm_w, h16);

    // 2) qkv16 = h16 @ wqkv^T
    gemm_cp<__half><<<dim3(S / BM, QKV_DIM / BN, 1), 256, SMEM>>>(
        h16, wqkv16, qkv16, DIM, DIM, DIM, QKV_DIM, nullptr);

    // 3) q/k layernorm + rope (in place)
    qknorm_rope_h<<<dim3(S, NH + NKV), HD>>>(qkv16, qn_w, qn_b, kn_w, kn_b, fcos, fsin);

    // 4) vt16 = V^T
    transpose_v<<<dim3(S / 32, (NKV * HD) / 32), dim3(32, 8)>>>(qkv16, vt16);

    // 5) fused flash attention -> o16
    flash_attn<<<dim3(16, 16), 256, FSMEM>>>(qkv16, vt16, o16);

    // 6) h2 = x + o @ wo^T (residual fused into epilogue)
    gemm_cp<float><<<dim3(S / BM, DIM / BN, 1), 256, SMEM>>>(
        o16, wo16, h2, DIM, DIM, DIM, DIM, x);

    // 7) h16 = rmsnorm(h2)
    rmsnorm_h<<<S, 256>>>(h2, ffn_norm_w, h16);

    // 8) x13_16 = g @ w13^T
    gemm_cp<__half><<<dim3(S / BM, (2 * HID) / BN, 1), 256, SMEM>>>(
        h16, w13_16, x13_16, DIM, DIM, DIM, 2 * HID, nullptr);

    // 9) gate16 = silu(x1) * x3
    swiglu_h<<<(S * HID + 255) / 256, 256>>>(x13_16, gate16);

    // 10) out = h2 + gate @ w2^T (residual fused)
    gemm_cp<float><<<dim3(S / BM, DIM / BN, 1), 256, SMEM>>>(
        gate16, w2_16, out, HID, HID, HID, DIM, h2);
}

// round 8
// speedup vs baseline: 9.1485x; 1.1158x over previous
#include <cuda_runtime.h>
#include <cuda_fp16.h>
#include <math.h>
#include <stdint.h>

#define S 2048
#define DIM 2048
#define NH 16
#define NKV 8
#define HD 128
#define HID 5632
#define QKV_DIM ((NH + 2*NKV) * HD)   // 4096
#define VOFF ((NH + NKV) * HD)        // 3072
#define EPS 1e-5f

// ---------------- scratch ----------------
__device__ __align__(256) __half g_h16[(size_t)S * DIM];
__device__ __align__(256) __half g_qkv16[(size_t)S * QKV_DIM];
__device__ __align__(256) __half g_o16[(size_t)S * DIM];
__device__ __align__(256) __half g_x13_16[(size_t)S * 2 * HID];
__device__ __align__(256) __half g_gate16[(size_t)S * HID];
__device__ __align__(256) __half g_vt16[(size_t)NKV * HD * S];
__device__ __align__(256) __half g_wqkv16[(size_t)QKV_DIM * DIM];
__device__ __align__(256) __half g_wo16[(size_t)DIM * DIM];
__device__ __align__(256) __half g_w13_16[(size_t)2 * HID * DIM];
__device__ __align__(256) __half g_w2_16[(size_t)DIM * HID];
__device__ float g_h2[(size_t)S * DIM];

// ---------------- helpers ----------------
__device__ __forceinline__ uint32_t sm2u(const void* p) {
    uint32_t a;
    asm("{ .reg .u64 t; cvta.to.shared.u64 t, %1; cvt.u32.u64 %0, t; }" : "=r"(a) : "l"(p));
    return a;
}

// fp16 tile [128 rows][32 halves] = 8KB (GEMM operand staging)
__device__ __forceinline__ uint32_t smoff(uint32_t m, uint32_t k) {
    return (m >> 1) * 128u
         + (((((m & 1u) << 2) | (k >> 3)) ^ ((m >> 1) & 7u)) << 4)
         + (k & 7u) * 2u;
}

// fp16 tile [128 rows][128 halves] = 32KB (flash attention tiles)
__device__ __forceinline__ uint32_t smoff256(uint32_t r, uint32_t chunk) {
    return r * 256u + (((chunk ^ (r & 7u)) & 15u) << 4);
}

__device__ __forceinline__ uint4 ldm4(uint32_t addr) {
    uint4 r;
    asm volatile("ldmatrix.sync.aligned.m8n8.x4.shared.b16 {%0,%1,%2,%3}, [%4];"
                 : "=r"(r.x), "=r"(r.y), "=r"(r.z), "=r"(r.w) : "r"(addr));
    return r;
}

__device__ __forceinline__ void mma_f16(float* c, const uint4& a, uint32_t b0, uint32_t b1) {
    asm volatile(
        "mma.sync.aligned.m16n8k16.row.col.f32.f16.f16.f32 "
        "{%0,%1,%2,%3}, {%4,%5,%6,%7}, {%8,%9}, {%0,%1,%2,%3};"
        : "+f"(c[0]), "+f"(c[1]), "+f"(c[2]), "+f"(c[3])
        : "r"(a.x), "r"(a.y), "r"(a.z), "r"(a.w), "r"(b0), "r"(b1));
}

__device__ __forceinline__ void cpasync16(uint32_t dst, const void* src) {
    asm volatile("cp.async.cg.shared.global [%0], [%1], 16;" :: "r"(dst), "l"(src) : "memory");
}
__device__ __forceinline__ void cpcommit() {
    asm volatile("cp.async.commit_group;" ::: "memory");
}
template<int N> __device__ __forceinline__ void cpwait() {
    asm volatile("cp.async.wait_group %0;" :: "n"(N) : "memory");
}

__device__ __forceinline__ uint32_t h2u(float a, float b) {
    __half2 h = __floats2half2_rn(a, b);
    return *reinterpret_cast<uint32_t*>(&h);
}
__device__ __forceinline__ void st2(float* p, float a, float b) {
    *reinterpret_cast<float2*>(p) = make_float2(a, b);
}
__device__ __forceinline__ void st2(__half* p, float a, float b) {
    *reinterpret_cast<__half2*>(p) = __floats2half2_rn(a, b);
}

// ---------------- fp16 cp.async NT GEMM ----------------
// C[M,N] = A[M,K] @ B[N,K]^T (+ optional fp32 residual).
// 128x128x32 CTA tile, 128 threads: 2x2 warps with 64x64 warp tiles
// (16 ldmatrix.x4 per 64 HMMA per warp-iter -> tensor-bound, not LDS-bound).
// 4-stage cp.async pipeline, one-commit-per-iteration invariant.
#define BM 128
#define BN 128
#define BK 32
#define ATILE_B 8192
#define STAGE_B 16384
#define NSTAGE 4

template<typename OutT>
__global__ void __launch_bounds__(128, 2)
gemm_cp(const __half* __restrict__ A, const __half* __restrict__ B, OutT* __restrict__ C,
        int K, int lda, int ldb, int ldc, const float* __restrict__ res)
{
    int bm = blockIdx.x * BM;
    int bn = blockIdx.y * BN;

    extern __shared__ unsigned char smraw[];
    uint32_t smB = (sm2u(smraw) + 1023) & ~1023u;

    int tid  = threadIdx.x;
    int lane = tid & 31;
    int warp = tid >> 5;      // 0..3
    int wm = warp >> 1;       // 0..1
    int wn = warp & 1;        // 0..1

    int nCh = K / BK;

    // producer: 4 chunks per tile per thread. chunk c = tid + 128*q:
    // row = (tid>>2) + 32*q, kc = (tid&3)*8
    int pr  = tid >> 2;
    int kc0 = (tid & 3) * 8;
    const __half* Ag = A + (long long)bm * lda;
    const __half* Bg = B + (long long)bn * ldb;
    uint32_t so[4];
    #pragma unroll
    for (int q = 0; q < 4; ++q) so[q] = smoff(pr + 32 * q, kc0);

    auto issue = [&](int c) {
        uint32_t aB = smB + (c & (NSTAGE - 1)) * STAGE_B;
        uint32_t bB = aB + ATILE_B;
        int k0 = c * BK + kc0;
        #pragma unroll
        for (int q = 0; q < 4; ++q)
            cpasync16(aB + so[q], Ag + (long long)(pr + 32 * q) * lda + k0);
        #pragma unroll
        for (int q = 0; q < 4; ++q)
            cpasync16(bB + so[q], Bg + (long long)(pr + 32 * q) * ldb + k0);
        cpcommit();
    };

    // consumer ldmatrix base addresses (ks=0; ks=1 is XOR 32)
    uint32_t aAdr[4], bAdr[4];
    {
        int mi = lane >> 3;
        int ra = (lane & 7) + (mi & 1) * 8;
        int ka = (mi >> 1) * 8;
        #pragma unroll
        for (int g = 0; g < 4; ++g) aAdr[g] = smoff(wm * 64 + g * 16 + ra, ka);
        int rb = (lane & 7) + (mi >> 1) * 8;
        int kb = (mi & 1) * 8;
        #pragma unroll
        for (int g = 0; g < 4; ++g) bAdr[g] = smoff(wn * 64 + g * 16 + rb, kb);
    }

    float acc[4][8][4];
    #pragma unroll
    for (int a = 0; a < 4; ++a)
        #pragma unroll
        for (int b = 0; b < 8; ++b)
            #pragma unroll
            for (int c = 0; c < 4; ++c) acc[a][b][c] = 0.f;

    #pragma unroll
    for (int c = 0; c < 3; ++c) {
        if (c < nCh) issue(c);
        else cpcommit();
    }

    for (int it = 0; it < nCh; ++it) {
        cpwait<2>();
        __syncthreads();
        if (it + 3 < nCh) issue(it + 3);
        else cpcommit();

        uint32_t aB = smB + (it & (NSTAGE - 1)) * STAGE_B;
        uint32_t bB = aB + ATILE_B;

        #pragma unroll
        for (int ks = 0; ks < 2; ++ks) {
            uint32_t kx = ks ? 32u : 0u;
            uint4 av[4], bv[4];
            #pragma unroll
            for (int g = 0; g < 4; ++g) av[g] = ldm4(aB + (aAdr[g] ^ kx));
            #pragma unroll
            for (int g = 0; g < 4; ++g) bv[g] = ldm4(bB + (bAdr[g] ^ kx));
            #pragma unroll
            for (int mi = 0; mi < 4; ++mi) {
                #pragma unroll
                for (int nj = 0; nj < 8; ++nj) {
                    uint32_t b0 = (nj & 1) ? bv[nj >> 1].z : bv[nj >> 1].x;
                    uint32_t b1 = (nj & 1) ? bv[nj >> 1].w : bv[nj >> 1].y;
                    mma_f16(acc[mi][nj], av[mi], b0, b1);
                }
            }
        }
    }
    cpwait<0>();

    int grp = lane >> 2;
    int tg  = lane & 3;
    #pragma unroll
    for (int mi = 0; mi < 4; ++mi) {
        long long r0 = bm + wm * 64 + mi * 16 + grp;
        #pragma unroll
        for (int nj = 0; nj < 8; ++nj) {
            int c0 = bn + wn * 64 + nj * 8 + tg * 2;
            float v0 = acc[mi][nj][0], v1 = acc[mi][nj][1];
            float v2 = acc[mi][nj][2], v3 = acc[mi][nj][3];
            if (res) {
                float2 r01 = *reinterpret_cast<const float2*>(&res[r0 * ldc + c0]);
                float2 r23 = *reinterpret_cast<const float2*>(&res[(r0 + 8) * ldc + c0]);
                v0 += r01.x; v1 += r01.y; v2 += r23.x; v3 += r23.y;
            }
            st2(&C[r0 * ldc + c0],       v0, v1);
            st2(&C[(r0 + 8) * ldc + c0], v2, v3);
        }
    }
}

// ---------------- fused flash attention ----------------
__global__ void __launch_bounds__(256)
flash_attn(const __half* __restrict__ qkv, const __half* __restrict__ vt,
           __half* __restrict__ o)
{
    int qb = 15 - blockIdx.x;
    int h  = blockIdx.y;
    int nb = qb + 1;

    extern __shared__ unsigned char smraw[];
    uint32_t smQ = (sm2u(smraw) + 255) & ~255u;
    uint32_t smK = smQ + 32768;
    uint32_t smV = smK + 2 * 32768;

    int tid  = threadIdx.x;
    int lane = tid & 31;
    int warp = tid >> 5;
    int wrow = warp * 16;
    int grp  = lane >> 2;
    int tg   = lane & 3;

    const __half* Qg = qkv + (size_t)(qb * 128) * QKV_DIM + h * HD;
    const __half* Kg = qkv + NH * HD + (h >> 1) * HD;
    const __half* Vg = vt + (size_t)((h >> 1) * HD) * S;

    int prow = tid >> 1;
    int pc0  = (tid & 1) * 8;

    auto issueQ = [&]() {
        #pragma unroll
        for (int i = 0; i < 8; ++i) {
            int ch = pc0 + i;
            cpasync16(smQ + smoff256(prow, ch), Qg + (size_t)prow * QKV_DIM + ch * 8);
        }
    };
    auto issueKV = [&](int b) {
        uint32_t kB = smK + (b & 1) * 32768;
        uint32_t vB = smV + (b & 1) * 32768;
        #pragma unroll
        for (int i = 0; i < 8; ++i) {
            int ch = pc0 + i;
            uint32_t off = smoff256(prow, ch);
            cpasync16(kB + off, Kg + (size_t)(b * 128 + prow) * QKV_DIM + ch * 8);
            cpasync16(vB + off, Vg + (size_t)prow * S + b * 128 + ch * 8);
        }
    };

    issueQ();
    issueKV(0);
    cpcommit();

    int mi   = lane >> 3;
    int frow = (lane & 7) + (mi & 1) * 8;
    int fkc  = (mi >> 1);
    int brow = (lane & 7) + (mi >> 1) * 8;
    int bkc  = (mi & 1);

    float m0 = -1e30f, m1 = -1e30f, l0 = 0.f, l1 = 0.f;
    float O[16][4];
    #pragma unroll
    for (int j = 0; j < 16; ++j)
        #pragma unroll
        for (int c = 0; c < 4; ++c) O[j][c] = 0.f;

    uint4 qf[8];
    const float CS = 0.1275447941f;   // (1/sqrt(128)) * log2(e)

    for (int b = 0; b < nb; ++b) {
        cpwait<0>();
        __syncthreads();

        if (b == 0) {
            #pragma unroll
            for (int ks = 0; ks < 8; ++ks)
                qf[ks] = ldm4(smQ + smoff256(wrow + frow, ks * 2 + fkc));
        }
        if (b + 1 < nb) { issueKV(b + 1); cpcommit(); }

        uint32_t kB = smK + (b & 1) * 32768;
        uint32_t vB = smV + (b & 1) * 32768;

        float Sv[16][4];
        #pragma unroll
        for (int j = 0; j < 16; ++j)
            #pragma unroll
            for (int c = 0; c < 4; ++c) Sv[j][c] = 0.f;

        #pragma unroll
        for (int ks = 0; ks < 8; ++ks) {
            #pragma unroll
            for (int g = 0; g < 8; ++g) {
                uint4 bv = ldm4(kB + smoff256(g * 16 + brow, ks * 2 + bkc));
                mma_f16(Sv[2 * g],     qf[ks], bv.x, bv.y);
                mma_f16(Sv[2 * g + 1], qf[ks], bv.z, bv.w);
            }
        }

        if (b == qb) {
            int r0 = wrow + grp;
            #pragma unroll
            for (int j = 0; j < 16; ++j) {
                int c0 = j * 8 + tg * 2;
                if (c0     > r0)     Sv[j][0] = -1e30f;
                if (c0 + 1 > r0)     Sv[j][1] = -1e30f;
                if (c0     > r0 + 8) Sv[j][2] = -1e30f;
                if (c0 + 1 > r0 + 8) Sv[j][3] = -1e30f;
            }
        }

        float bm0 = -1e30f, bm1 = -1e30f;
        #pragma unroll
        for (int j = 0; j < 16; ++j) {
            bm0 = fmaxf(bm0, fmaxf(Sv[j][0], Sv[j][1]));
            bm1 = fmaxf(bm1, fmaxf(Sv[j][2], Sv[j][3]));
        }
        bm0 = fmaxf(bm0, __shfl_xor_sync(0xffffffffu, bm0, 1));
        bm0 = fmaxf(bm0, __shfl_xor_sync(0xffffffffu, bm0, 2));
        bm1 = fmaxf(bm1, __shfl_xor_sync(0xffffffffu, bm1, 1));
        bm1 = fmaxf(bm1, __shfl_xor_sync(0xffffffffu, bm1, 2));

        float nm0 = fmaxf(m0, bm0), nm1 = fmaxf(m1, bm1);
        float sc0 = exp2f((m0 - nm0) * CS), sc1 = exp2f((m1 - nm1) * CS);
        m0 = nm0; m1 = nm1;

        float rs0 = 0.f, rs1 = 0.f;
        #pragma unroll
        for (int j = 0; j < 16; ++j) {
            Sv[j][0] = exp2f((Sv[j][0] - nm0) * CS); rs0 += Sv[j][0];
            Sv[j][1] = exp2f((Sv[j][1] - nm0) * CS); rs0 += Sv[j][1];
            Sv[j][2] = exp2f((Sv[j][2] - nm1) * CS); rs1 += Sv[j][2];
            Sv[j][3] = exp2f((Sv[j][3] - nm1) * CS); rs1 += Sv[j][3];
        }
        l0 = l0 * sc0 + rs0;
        l1 = l1 * sc1 + rs1;

        #pragma unroll
        for (int j = 0; j < 16; ++j) {
            O[j][0] *= sc0; O[j][1] *= sc0;
            O[j][2] *= sc1; O[j][3] *= sc1;
        }

        #pragma unroll
        for (int ks = 0; ks < 8; ++ks) {
            uint4 pa;
            pa.x = h2u(Sv[2 * ks][0],     Sv[2 * ks][1]);
            pa.y = h2u(Sv[2 * ks][2],     Sv[2 * ks][3]);
            pa.z = h2u(Sv[2 * ks + 1][0], Sv[2 * ks + 1][1]);
            pa.w = h2u(Sv[2 * ks + 1][2], Sv[2 * ks + 1][3]);
            #pragma unroll
            for (int g = 0; g < 8; ++g) {
                uint4 bv = ldm4(vB + smoff256(g * 16 + brow, ks * 2 + bkc));
                mma_f16(O[2 * g],     pa, bv.x, bv.y);
                mma_f16(O[2 * g + 1], pa, bv.z, bv.w);
            }
        }
    }

    l0 += __shfl_xor_sync(0xffffffffu, l0, 1);
    l0 += __shfl_xor_sync(0xffffffffu, l0, 2);
    l1 += __shfl_xor_sync(0xffffffffu, l1, 1);
    l1 += __shfl_xor_sync(0xffffffffu, l1, 2);
    float inv0 = 1.f / l0, inv1 = 1.f / l1;

    __half* o0 = o + (size_t)(qb * 128 + wrow + grp) * DIM + h * HD;
    __half* o1 = o0 + 8 * DIM;
    #pragma unroll
    for (int j = 0; j < 16; ++j) {
        int c0 = j * 8 + tg * 2;
        st2(o0 + c0, O[j][0] * inv0, O[j][1] * inv0);
        st2(o1 + c0, O[j][2] * inv1, O[j][3] * inv1);
    }
}

// ---------------- fp32 -> fp16 ----------------
__global__ void f2h_kernel(const float* __restrict__ in, __half* __restrict__ out, long long n)
{
    long long i = ((long long)blockIdx.x * 256 + threadIdx.x) * 4;
    if (i < n) {
        float4 v = *reinterpret_cast<const float4*>(in + i);
        *reinterpret_cast<__half2*>(out + i)     = __floats2half2_rn(v.x, v.y);
        *reinterpret_cast<__half2*>(out + i + 2) = __floats2half2_rn(v.z, v.w);
    }
}

// ---------------- V transpose ----------------
__global__ void transpose_v(const __half* __restrict__ qkv, __half* __restrict__ vt)
{
    __shared__ float t[32][33];
    int s0 = blockIdx.x * 32;
    int d0 = blockIdx.y * 32;
    int tx = threadIdx.x, ty = threadIdx.y;
    #pragma unroll
    for (int j = 0; j < 32; j += 8)
        t[ty + j][tx] = __half2float(qkv[(long long)(s0 + ty + j) * QKV_DIM + VOFF + d0 + tx]);
    __syncthreads();
    #pragma unroll
    for (int j = 0; j < 32; j += 8)
        vt[(long long)(d0 + ty + j) * S + s0 + tx] = __float2half_rn(t[tx][ty + j]);
}

// ---------------- norm / elementwise ----------------
__global__ void rmsnorm_h(const float* __restrict__ x, const float* __restrict__ w,
                          __half* __restrict__ out)
{
    int row = blockIdx.x;
    const float* xr = x + (long long)row * DIM;
    __shared__ float red[256];
    int t = threadIdx.x;
    float s = 0.f;
    for (int i = t; i < DIM; i += 256) { float v = xr[i]; s += v * v; }
    red[t] = s; __syncthreads();
    for (int o = 128; o > 0; o >>= 1) { if (t < o) red[t] += red[t + o]; __syncthreads(); }
    float inv = rsqrtf(red[0] / (float)DIM + EPS);
    __half* orow = out + (long long)row * DIM;
    for (int i = t; i < DIM; i += 256) orow[i] = __float2half_rn(xr[i] * inv * w[i]);
}

__global__ void qknorm_rope_h(__half* __restrict__ qkv,
                              const float* __restrict__ qn_w, const float* __restrict__ qn_b,
                              const float* __restrict__ kn_w, const float* __restrict__ kn_b,
                              const float* __restrict__ fcos, const float* __restrict__ fsin)
{
    int s = blockIdx.x;
    int h = blockIdx.y;
    bool isq = (h < NH);
    int col = isq ? h * HD : NH * HD + (h - NH) * HD;
    __half* p = qkv + (long long)s * QKV_DIM + col;
    const float* w = isq ? qn_w : kn_w;
    const float* b = isq ? qn_b : kn_b;

    int t = threadIdx.x;
    float v = __half2float(p[t]);

    __shared__ float sm[4], sv[4];
    float m = v;
    #pragma unroll
    for (int o = 16; o; o >>= 1) m += __shfl_xor_sync(0xffffffffu, m, o);
    if ((t & 31) == 0) sm[t >> 5] = m;
    __syncthreads();
    float mean = (sm[0] + sm[1] + sm[2] + sm[3]) * (1.f / HD);
    float d = v - mean;
    float vv = d * d;
    #pragma unroll
    for (int o = 16; o; o >>= 1) vv += __shfl_xor_sync(0xffffffffu, vv, o);
    if ((t & 31) == 0) sv[t >> 5] = vv;
    __syncthreads();
    float var = (sv[0] + sv[1] + sv[2] + sv[3]) * (1.f / HD);
    float n = d * rsqrtf(var + EPS) * w[t] + b[t];

    __shared__ float sh[HD];
    sh[t] = n; __syncthreads();

    float c  = fcos[(long long)s * (HD / 2) + (t >> 1)];
    float si = fsin[(long long)s * (HD / 2) + (t >> 1)];
    float x0 = sh[t & ~1];
    float x1 = sh[t | 1];
    float r  = ((t & 1) == 0) ? (x0 * c - x1 * si) : (x0 * si + x1 * c);
    p[t] = __float2half_rn(r);
}

__global__ void swiglu_h(const __half* __restrict__ x13, __half* __restrict__ gate)
{
    unsigned idx = blockIdx.x * 256u + threadIdx.x;
    if (idx >= (unsigned)(S * HID)) return;
    unsigned s = idx / HID;
    unsigned j = idx - s * HID;
    float a = __half2float(x13[(size_t)s * (2 * HID) + j]);
    float b = __half2float(x13[(size_t)s * (2 * HID) + HID + j]);
    float sig = 1.f / (1.f + expf(-a));
    gate[idx] = __float2half_rn(a * sig * b);
}

// ---------------- launcher ----------------
extern "C" void kernel_launch(void* const* d_in, const int* in_sizes, int n_in,
                              void* d_out, int out_size)
{
    const float* x           = (const float*)d_in[0];
    const float* fcos        = (const float*)d_in[1];
    const float* fsin        = (const float*)d_in[2];
    const float* wqkv        = (const float*)d_in[4];
    const float* wo          = (const float*)d_in[5];
    const float* qn_w        = (const float*)d_in[6];
    const float* qn_b        = (const float*)d_in[7];
    const float* kn_w        = (const float*)d_in[8];
    const float* kn_b        = (const float*)d_in[9];
    const float* attn_norm_w = (const float*)d_in[10];
    const float* ffn_norm_w  = (const float*)d_in[11];
    const float* w13         = (const float*)d_in[12];
    const float* w2          = (const float*)d_in[13];
    float* out = (float*)d_out;

    __half *h16, *qkv16, *o16, *x13_16, *gate16, *vt16;
    __half *wqkv16, *wo16, *w13_16, *w2_16;
    float *h2;
    cudaGetSymbolAddress((void**)&h16,     g_h16);
    cudaGetSymbolAddress((void**)&qkv16,   g_qkv16);
    cudaGetSymbolAddress((void**)&o16,     g_o16);
    cudaGetSymbolAddress((void**)&x13_16,  g_x13_16);
    cudaGetSymbolAddress((void**)&gate16,  g_gate16);
    cudaGetSymbolAddress((void**)&vt16,    g_vt16);
    cudaGetSymbolAddress((void**)&wqkv16,  g_wqkv16);
    cudaGetSymbolAddress((void**)&wo16,    g_wo16);
    cudaGetSymbolAddress((void**)&w13_16,  g_w13_16);
    cudaGetSymbolAddress((void**)&w2_16,   g_w2_16);
    cudaGetSymbolAddress((void**)&h2,      g_h2);

    const int SMEM = NSTAGE * STAGE_B + 1024;          // 65 KB + pad
    const int FSMEM = 5 * 32768 + 256;                 // 160 KB + pad
    cudaFuncSetAttribute(gemm_cp<float>,  cudaFuncAttributeMaxDynamicSharedMemorySize, SMEM);
    cudaFuncSetAttribute(gemm_cp<__half>, cudaFuncAttributeMaxDynamicSharedMemorySize, SMEM);
    cudaFuncSetAttribute(flash_attn,      cudaFuncAttributeMaxDynamicSharedMemorySize, FSMEM);

    // 0) weights -> fp16
    f2h_kernel<<<(QKV_DIM * (long long)DIM) / 1024, 256>>>(wqkv, wqkv16, (long long)QKV_DIM * DIM);
    f2h_kernel<<<((long long)DIM * DIM) / 1024, 256>>>(wo, wo16, (long long)DIM * DIM);
    f2h_kernel<<<(2LL * HID * DIM) / 1024, 256>>>(w13, w13_16, 2LL * HID * DIM);
    f2h_kernel<<<((long long)DIM * HID) / 1024, 256>>>(w2, w2_16, (long long)DIM * HID);

    // 1) h16 = rmsnorm(x)
    rmsnorm_h<<<S, 256>>>(x, attn_norm_w, h16);

    // 2) qkv16 = h16 @ wqkv^T
    gemm_cp<__half><<<dim3(S / BM, QKV_DIM / BN, 1), 128, SMEM>>>(
        h16, wqkv16, qkv16, DIM, DIM, DIM, QKV_DIM, nullptr);

    // 3) q/k layernorm + rope (in place)
    qknorm_rope_h<<<dim3(S, NH + NKV), HD>>>(qkv16, qn_w, qn_b, kn_w, kn_b, fcos, fsin);

    // 4) vt16 = V^T
    transpose_v<<<dim3(S / 32, (NKV * HD) / 32), dim3(32, 8)>>>(qkv16, vt16);

    // 5) fused flash attention -> o16
    flash_attn<<<dim3(16, 16), 256, FSMEM>>>(qkv16, vt16, o16);

    // 6) h2 = x + o @ wo^T (residual fused)
    gemm_cp<float><<<dim3(S / BM, DIM / BN, 1), 128, SMEM>>>(
        o16, wo16, h2, DIM, DIM, DIM, DIM, x);

    // 7) h16 = rmsnorm(h2)
    rmsnorm_h<<<S, 256>>>(h2, ffn_norm_w, h16);

    // 8) x13_16 = g @ w13^T
    gemm_cp<__half><<<dim3(S / BM, (2 * HID) / BN, 1), 128, SMEM>>>(
        h16, w13_16, x13_16, DIM, DIM, DIM, 2 * HID, nullptr);

    // 9) gate16 = silu(x1) * x3
    swiglu_h<<<(S * HID + 255) / 256, 256>>>(x13_16, gate16);

    // 10) out = h2 + gate @ w2^T (residual fused)
    gemm_cp<float><<<dim3(S / BM, DIM / BN, 1), 128, SMEM>>>(
        gate16, w2_16, out, HID, HID, HID, DIM, h2);
}

// round 9
// speedup vs baseline: 9.6921x; 1.0594x over previous
#include <cuda_runtime.h>
#include <cuda_fp16.h>
#include <math.h>
#include <stdint.h>

#define S 2048
#define DIM 2048
#define NH 16
#define NKV 8
#define HD 128
#define HID 5632
#define QKV_DIM ((NH + 2*NKV) * HD)   // 4096
#define VOFF ((NH + NKV) * HD)        // 3072
#define EPS 1e-5f

// ---------------- scratch ----------------
__device__ __align__(256) __half g_h16[(size_t)S * DIM];
__device__ __align__(256) __half g_qkv16[(size_t)S * QKV_DIM];
__device__ __align__(256) __half g_o16[(size_t)S * DIM];
__device__ __align__(256) __half g_gate16[(size_t)S * HID];
__device__ __align__(256) __half g_vt16[(size_t)NKV * HD * S];
__device__ __align__(256) __half g_wqkv16[(size_t)QKV_DIM * DIM];
__device__ __align__(256) __half g_wo16[(size_t)DIM * DIM];
__device__ __align__(256) __half g_w13_16[(size_t)2 * HID * DIM];  // interleaved (w1_j,w3_j)
__device__ __align__(256) __half g_w2_16[(size_t)DIM * HID];
__device__ float g_h2[(size_t)S * DIM];

// ---------------- helpers ----------------
__device__ __forceinline__ uint32_t sm2u(const void* p) {
    uint32_t a;
    asm("{ .reg .u64 t; cvta.to.shared.u64 t, %1; cvt.u32.u64 %0, t; }" : "=r"(a) : "l"(p));
    return a;
}

__device__ __forceinline__ uint32_t smoff(uint32_t m, uint32_t k) {
    return (m >> 1) * 128u
         + (((((m & 1u) << 2) | (k >> 3)) ^ ((m >> 1) & 7u)) << 4)
         + (k & 7u) * 2u;
}
__device__ __forceinline__ uint32_t smoff256(uint32_t r, uint32_t chunk) {
    return r * 256u + (((chunk ^ (r & 7u)) & 15u) << 4);
}

__device__ __forceinline__ uint4 ldm4(uint32_t addr) {
    uint4 r;
    asm volatile("ldmatrix.sync.aligned.m8n8.x4.shared.b16 {%0,%1,%2,%3}, [%4];"
                 : "=r"(r.x), "=r"(r.y), "=r"(r.z), "=r"(r.w) : "r"(addr));
    return r;
}

__device__ __forceinline__ void mma_f16(float* c, const uint4& a, uint32_t b0, uint32_t b1) {
    asm volatile(
        "mma.sync.aligned.m16n8k16.row.col.f32.f16.f16.f32 "
        "{%0,%1,%2,%3}, {%4,%5,%6,%7}, {%8,%9}, {%0,%1,%2,%3};"
        : "+f"(c[0]), "+f"(c[1]), "+f"(c[2]), "+f"(c[3])
        : "r"(a.x), "r"(a.y), "r"(a.z), "r"(a.w), "r"(b0), "r"(b1));
}

__device__ __forceinline__ void cpasync16(uint32_t dst, const void* src) {
    asm volatile("cp.async.cg.shared.global [%0], [%1], 16;" :: "r"(dst), "l"(src) : "memory");
}
__device__ __forceinline__ void cpcommit() {
    asm volatile("cp.async.commit_group;" ::: "memory");
}
template<int N> __device__ __forceinline__ void cpwait() {
    asm volatile("cp.async.wait_group %0;" :: "n"(N) : "memory");
}

__device__ __forceinline__ uint32_t h2u(float a, float b) {
    __half2 h = __floats2half2_rn(a, b);
    return *reinterpret_cast<uint32_t*>(&h);
}
__device__ __forceinline__ void st2(float* p, float a, float b) {
    *reinterpret_cast<float2*>(p) = make_float2(a, b);
}
__device__ __forceinline__ void st2(__half* p, float a, float b) {
    *reinterpret_cast<__half2*>(p) = __floats2half2_rn(a, b);
}
__device__ __forceinline__ float wredsum(float v) {
    #pragma unroll
    for (int o = 16; o; o >>= 1) v += __shfl_xor_sync(0xffffffffu, v, o);
    return v;
}

// ---------------- fp16 cp.async NT GEMM (2x2 warps, 64x64 warp tiles) ----------------
#define BM 128
#define BN 128
#define BK 32
#define ATILE_B 8192
#define STAGE_B 16384
#define NSTAGE 4

template<typename OutT, bool SWIGLU>
__global__ void __launch_bounds__(128, 2)
gemm_cp(const __half* __restrict__ A, const __half* __restrict__ B, OutT* __restrict__ C,
        int K, int lda, int ldb, int ldc, const float* __restrict__ res)
{
    int bm = blockIdx.x * BM;
    int bn = blockIdx.y * BN;

    extern __shared__ unsigned char smraw[];
    uint32_t smB = (sm2u(smraw) + 1023) & ~1023u;

    int tid  = threadIdx.x;
    int lane = tid & 31;
    int warp = tid >> 5;
    int wm = warp >> 1;
    int wn = warp & 1;

    int nCh = K / BK;

    int pr  = tid >> 2;
    int kc0 = (tid & 3) * 8;
    const __half* Ag = A + (long long)bm * lda;
    const __half* Bg = B + (long long)bn * ldb;
    uint32_t so[4];
    #pragma unroll
    for (int q = 0; q < 4; ++q) so[q] = smoff(pr + 32 * q, kc0);

    auto issue = [&](int c) {
        uint32_t aB = smB + (c & (NSTAGE - 1)) * STAGE_B;
        uint32_t bB = aB + ATILE_B;
        int k0 = c * BK + kc0;
        #pragma unroll
        for (int q = 0; q < 4; ++q)
            cpasync16(aB + so[q], Ag + (long long)(pr + 32 * q) * lda + k0);
        #pragma unroll
        for (int q = 0; q < 4; ++q)
            cpasync16(bB + so[q], Bg + (long long)(pr + 32 * q) * ldb + k0);
        cpcommit();
    };

    uint32_t aAdr[4], bAdr[4];
    {
        int mi = lane >> 3;
        int ra = (lane & 7) + (mi & 1) * 8;
        int ka = (mi >> 1) * 8;
        #pragma unroll
        for (int g = 0; g < 4; ++g) aAdr[g] = smoff(wm * 64 + g * 16 + ra, ka);
        int rb = (lane & 7) + (mi >> 1) * 8;
        int kb = (mi & 1) * 8;
        #pragma unroll
        for (int g = 0; g < 4; ++g) bAdr[g] = smoff(wn * 64 + g * 16 + rb, kb);
    }

    float acc[4][8][4];
    #pragma unroll
    for (int a = 0; a < 4; ++a)
        #pragma unroll
        for (int b = 0; b < 8; ++b)
            #pragma unroll
            for (int c = 0; c < 4; ++c) acc[a][b][c] = 0.f;

    #pragma unroll
    for (int c = 0; c < 3; ++c) {
        if (c < nCh) issue(c);
        else cpcommit();
    }

    for (int it = 0; it < nCh; ++it) {
        cpwait<2>();
        __syncthreads();
        if (it + 3 < nCh) issue(it + 3);
        else cpcommit();

        uint32_t aB = smB + (it & (NSTAGE - 1)) * STAGE_B;
        uint32_t bB = aB + ATILE_B;

        #pragma unroll
        for (int ks = 0; ks < 2; ++ks) {
            uint32_t kx = ks ? 32u : 0u;
            uint4 av[4], bv[4];
            #pragma unroll
            for (int g = 0; g < 4; ++g) av[g] = ldm4(aB + (aAdr[g] ^ kx));
            #pragma unroll
            for (int g = 0; g < 4; ++g) bv[g] = ldm4(bB + (bAdr[g] ^ kx));
            #pragma unroll
            for (int mi = 0; mi < 4; ++mi) {
                #pragma unroll
                for (int nj = 0; nj < 8; ++nj) {
                    uint32_t b0 = (nj & 1) ? bv[nj >> 1].z : bv[nj >> 1].x;
                    uint32_t b1 = (nj & 1) ? bv[nj >> 1].w : bv[nj >> 1].y;
                    mma_f16(acc[mi][nj], av[mi], b0, b1);
                }
            }
        }
    }
    cpwait<0>();

    int grp = lane >> 2;
    int tg  = lane & 3;
    #pragma unroll
    for (int mi = 0; mi < 4; ++mi) {
        long long r0 = bm + wm * 64 + mi * 16 + grp;
        #pragma unroll
        for (int nj = 0; nj < 8; ++nj) {
            int cl = wn * 64 + nj * 8 + tg * 2;   // even
            if (SWIGLU) {
                // (v0,v1) = (x1_p, x3_p) at pair p = (bn+cl)/2; likewise (v2,v3) at r0+8
                int p = (bn + cl) >> 1;
                float a0 = acc[mi][nj][0], b0v = acc[mi][nj][1];
                float a1 = acc[mi][nj][2], b1v = acc[mi][nj][3];
                float g0 = a0 * b0v / (1.f + expf(-a0));
                float g1 = a1 * b1v / (1.f + expf(-a1));
                __half* Ch = (__half*)C;
                Ch[r0 * ldc + p]       = __float2half_rn(g0);
                Ch[(r0 + 8) * ldc + p] = __float2half_rn(g1);
            } else {
                int c0 = bn + cl;
                float v0 = acc[mi][nj][0], v1 = acc[mi][nj][1];
                float v2 = acc[mi][nj][2], v3 = acc[mi][nj][3];
                if (res) {
                    float2 r01 = *reinterpret_cast<const float2*>(&res[r0 * ldc + c0]);
                    float2 r23 = *reinterpret_cast<const float2*>(&res[(r0 + 8) * ldc + c0]);
                    v0 += r01.x; v1 += r01.y; v2 += r23.x; v3 += r23.y;
                }
                st2(&C[r0 * ldc + c0],       v0, v1);
                st2(&C[(r0 + 8) * ldc + c0], v2, v3);
            }
        }
    }
}

// ---------------- fused flash attention ----------------
__global__ void __launch_bounds__(256)
flash_attn(const __half* __restrict__ qkv, const __half* __restrict__ vt,
           __half* __restrict__ o)
{
    int qb = 15 - blockIdx.x;
    int h  = blockIdx.y;
    int nb = qb + 1;

    extern __shared__ unsigned char smraw[];
    uint32_t smQ = (sm2u(smraw) + 255) & ~255u;
    uint32_t smK = smQ + 32768;
    uint32_t smV = smK + 2 * 32768;

    int tid  = threadIdx.x;
    int lane = tid & 31;
    int warp = tid >> 5;
    int wrow = warp * 16;
    int grp  = lane >> 2;
    int tg   = lane & 3;

    const __half* Qg = qkv + (size_t)(qb * 128) * QKV_DIM + h * HD;
    const __half* Kg = qkv + NH * HD + (h >> 1) * HD;
    const __half* Vg = vt + (size_t)((h >> 1) * HD) * S;

    int prow = tid >> 1;
    int pc0  = (tid & 1) * 8;

    auto issueQ = [&]() {
        #pragma unroll
        for (int i = 0; i < 8; ++i) {
            int ch = pc0 + i;
            cpasync16(smQ + smoff256(prow, ch), Qg + (size_t)prow * QKV_DIM + ch * 8);
        }
    };
    auto issueKV = [&](int b) {
        uint32_t kB = smK + (b & 1) * 32768;
        uint32_t vB = smV + (b & 1) * 32768;
        #pragma unroll
        for (int i = 0; i < 8; ++i) {
            int ch = pc0 + i;
            uint32_t off = smoff256(prow, ch);
            cpasync16(kB + off, Kg + (size_t)(b * 128 + prow) * QKV_DIM + ch * 8);
            cpasync16(vB + off, Vg + (size_t)prow * S + b * 128 + ch * 8);
        }
    };

    issueQ();
    issueKV(0);
    cpcommit();

    int mi   = lane >> 3;
    int frow = (lane & 7) + (mi & 1) * 8;
    int fkc  = (mi >> 1);
    int brow = (lane & 7) + (mi >> 1) * 8;
    int bkc  = (mi & 1);

    float m0 = -1e30f, m1 = -1e30f, l0 = 0.f, l1 = 0.f;
    float O[16][4];
    #pragma unroll
    for (int j = 0; j < 16; ++j)
        #pragma unroll
        for (int c = 0; c < 4; ++c) O[j][c] = 0.f;

    uint4 qf[8];
    const float CS = 0.1275447941f;   // (1/sqrt(128)) * log2(e)

    for (int b = 0; b < nb; ++b) {
        cpwait<0>();
        __syncthreads();

        if (b == 0) {
            #pragma unroll
            for (int ks = 0; ks < 8; ++ks)
                qf[ks] = ldm4(smQ + smoff256(wrow + frow, ks * 2 + fkc));
        }
        if (b + 1 < nb) { issueKV(b + 1); cpcommit(); }

        uint32_t kB = smK + (b & 1) * 32768;
        uint32_t vB = smV + (b & 1) * 32768;

        float Sv[16][4];
        #pragma unroll
        for (int j = 0; j < 16; ++j)
            #pragma unroll
            for (int c = 0; c < 4; ++c) Sv[j][c] = 0.f;

        #pragma unroll
        for (int ks = 0; ks < 8; ++ks) {
            #pragma unroll
            for (int g = 0; g < 8; ++g) {
                uint4 bv = ldm4(kB + smoff256(g * 16 + brow, ks * 2 + bkc));
                mma_f16(Sv[2 * g],     qf[ks], bv.x, bv.y);
                mma_f16(Sv[2 * g + 1], qf[ks], bv.z, bv.w);
            }
        }

        if (b == qb) {
            int r0 = wrow + grp;
            #pragma unroll
            for (int j = 0; j < 16; ++j) {
                int c0 = j * 8 + tg * 2;
                if (c0     > r0)     Sv[j][0] = -1e30f;
                if (c0 + 1 > r0)     Sv[j][1] = -1e30f;
                if (c0     > r0 + 8) Sv[j][2] = -1e30f;
                if (c0 + 1 > r0 + 8) Sv[j][3] = -1e30f;
            }
        }

        float bm0 = -1e30f, bm1 = -1e30f;
        #pragma unroll
        for (int j = 0; j < 16; ++j) {
            bm0 = fmaxf(bm0, fmaxf(Sv[j][0], Sv[j][1]));
            bm1 = fmaxf(bm1, fmaxf(Sv[j][2], Sv[j][3]));
        }
        bm0 = fmaxf(bm0, __shfl_xor_sync(0xffffffffu, bm0, 1));
        bm0 = fmaxf(bm0, __shfl_xor_sync(0xffffffffu, bm0, 2));
        bm1 = fmaxf(bm1, __shfl_xor_sync(0xffffffffu, bm1, 1));
        bm1 = fmaxf(bm1, __shfl_xor_sync(0xffffffffu, bm1, 2));

        float nm0 = fmaxf(m0, bm0), nm1 = fmaxf(m1, bm1);
        float sc0 = exp2f((m0 - nm0) * CS), sc1 = exp2f((m1 - nm1) * CS);
        m0 = nm0; m1 = nm1;

        float rs0 = 0.f, rs1 = 0.f;
        #pragma unroll
        for (int j = 0; j < 16; ++j) {
            Sv[j][0] = exp2f((Sv[j][0] - nm0) * CS); rs0 += Sv[j][0];
            Sv[j][1] = exp2f((Sv[j][1] - nm0) * CS); rs0 += Sv[j][1];
            Sv[j][2] = exp2f((Sv[j][2] - nm1) * CS); rs1 += Sv[j][2];
            Sv[j][3] = exp2f((Sv[j][3] - nm1) * CS); rs1 += Sv[j][3];
        }
        l0 = l0 * sc0 + rs0;
        l1 = l1 * sc1 + rs1;

        #pragma unroll
        for (int j = 0; j < 16; ++j) {
            O[j][0] *= sc0; O[j][1] *= sc0;
            O[j][2] *= sc1; O[j][3] *= sc1;
        }

        #pragma unroll
        for (int ks = 0; ks < 8; ++ks) {
            uint4 pa;
            pa.x = h2u(Sv[2 * ks][0],     Sv[2 * ks][1]);
            pa.y = h2u(Sv[2 * ks][2],     Sv[2 * ks][3]);
            pa.z = h2u(Sv[2 * ks + 1][0], Sv[2 * ks + 1][1]);
            pa.w = h2u(Sv[2 * ks + 1][2], Sv[2 * ks + 1][3]);
            #pragma unroll
            for (int g = 0; g < 8; ++g) {
                uint4 bv = ldm4(vB + smoff256(g * 16 + brow, ks * 2 + bkc));
                mma_f16(O[2 * g],     pa, bv.x, bv.y);
                mma_f16(O[2 * g + 1], pa, bv.z, bv.w);
            }
        }
    }

    l0 += __shfl_xor_sync(0xffffffffu, l0, 1);
    l0 += __shfl_xor_sync(0xffffffffu, l0, 2);
    l1 += __shfl_xor_sync(0xffffffffu, l1, 1);
    l1 += __shfl_xor_sync(0xffffffffu, l1, 2);
    float inv0 = 1.f / l0, inv1 = 1.f / l1;

    __half* o0 = o + (size_t)(qb * 128 + wrow + grp) * DIM + h * HD;
    __half* o1 = o0 + 8 * DIM;
    #pragma unroll
    for (int j = 0; j < 16; ++j) {
        int c0 = j * 8 + tg * 2;
        st2(o0 + c0, O[j][0] * inv0, O[j][1] * inv0);
        st2(o1 + c0, O[j][2] * inv1, O[j][3] * inv1);
    }
}

// ---------------- fp32 -> fp16, ILP 4 (16 floats / thread) ----------------
__global__ void f2h_kernel(const float* __restrict__ in, __half* __restrict__ out, long long n)
{
    long long i = ((long long)blockIdx.x * 256 + threadIdx.x) * 16;
    if (i >= n) return;
    float4 v[4];
    #pragma unroll
    for (int q = 0; q < 4; ++q)
        v[q] = *reinterpret_cast<const float4*>(in + i + q * 4);
    #pragma unroll
    for (int q = 0; q < 2; ++q) {
        uint4 o;
        o.x = h2u(v[2*q].x,   v[2*q].y);
        o.y = h2u(v[2*q].z,   v[2*q].w);
        o.z = h2u(v[2*q+1].x, v[2*q+1].y);
        o.w = h2u(v[2*q+1].z, v[2*q+1].w);
        *reinterpret_cast<uint4*>(out + i + q * 8) = o;
    }
}

// w13 interleave: out row 2j = w1 row j, row 2j+1 = w3 row j (fp16)
__global__ void f2h_w13(const float* __restrict__ in, __half* __restrict__ out)
{
    long long g = ((long long)blockIdx.x * 256 + threadIdx.x) * 8;   // 8 floats per row-stream
    if (g >= (long long)HID * DIM) return;
    long long j = g / DIM;
    long long c = g - j * DIM;
    #pragma unroll
    for (int s = 0; s < 2; ++s) {
        const float* src = in + ((s ? HID : 0) + j) * (long long)DIM + c;
        float4 a = *reinterpret_cast<const float4*>(src);
        float4 b = *reinterpret_cast<const float4*>(src + 4);
        uint4 o;
        o.x = h2u(a.x, a.y); o.y = h2u(a.z, a.w);
        o.z = h2u(b.x, b.y); o.w = h2u(b.z, b.w);
        *reinterpret_cast<uint4*>(out + (2 * j + s) * (long long)DIM + c) = o;
    }
}

// ---------------- V transpose ----------------
__global__ void transpose_v(const __half* __restrict__ qkv, __half* __restrict__ vt)
{
    __shared__ float t[32][33];
    int s0 = blockIdx.x * 32;
    int d0 = blockIdx.y * 32;
    int tx = threadIdx.x, ty = threadIdx.y;
    #pragma unroll
    for (int j = 0; j < 32; j += 8)
        t[ty + j][tx] = __half2float(qkv[(long long)(s0 + ty + j) * QKV_DIM + VOFF + d0 + tx]);
    __syncthreads();
    #pragma unroll
    for (int j = 0; j < 32; j += 8)
        vt[(long long)(d0 + ty + j) * S + s0 + tx] = __float2half_rn(t[tx][ty + j]);
}

// ---------------- warp-per-row rmsnorm (8 rows / 256-thr block) ----------------
__global__ void rmsnorm_h(const float* __restrict__ x, const float* __restrict__ w,
                          __half* __restrict__ out)
{
    int row  = blockIdx.x * 8 + (threadIdx.x >> 5);
    int lane = threadIdx.x & 31;
    const float* xr = x + (long long)row * DIM;

    float s = 0.f;
    float4 v[16];
    #pragma unroll
    for (int i = 0; i < 16; ++i) {
        v[i] = *reinterpret_cast<const float4*>(xr + lane * 4 + i * 128);
        s += v[i].x * v[i].x + v[i].y * v[i].y + v[i].z * v[i].z + v[i].w * v[i].w;
    }
    s = wredsum(s);
    float inv = rsqrtf(s / (float)DIM + EPS);

    __half* orow = out + (long long)row * DIM;
    #pragma unroll
    for (int i = 0; i < 16; ++i) {
        int c = lane * 4 + i * 128;
        uint2 o;
        o.x = h2u(v[i].x * inv * w[c],     v[i].y * inv * w[c + 1]);
        o.y = h2u(v[i].z * inv * w[c + 2], v[i].w * inv * w[c + 3]);
        *reinterpret_cast<uint2*>(orow + c) = o;
    }
}

// ---------------- warp-per-head layernorm + rope (shuffle only) ----------------
// grid (S, 3), 256 threads = 8 warps; warp handles head hh = by*8 + warp (0..23).
__global__ void qknorm_rope_h(__half* __restrict__ qkv,
                              const float* __restrict__ qn_w, const float* __restrict__ qn_b,
                              const float* __restrict__ kn_w, const float* __restrict__ kn_b,
                              const float* __restrict__ fcos, const float* __restrict__ fsin)
{
    int s    = blockIdx.x;
    int hh   = blockIdx.y * 8 + (threadIdx.x >> 5);
    int lane = threadIdx.x & 31;
    bool isq = (hh < NH);
    int col  = isq ? hh * HD : NH * HD + (hh - NH) * HD;
    __half* p = qkv + (long long)s * QKV_DIM + col + lane * 4;
    const float* w = (isq ? qn_w : kn_w) + lane * 4;
    const float* b = (isq ? qn_b : kn_b) + lane * 4;

    uint2 raw = *reinterpret_cast<const uint2*>(p);
    __half2 h01 = *reinterpret_cast<__half2*>(&raw.x);
    __half2 h23 = *reinterpret_cast<__half2*>(&raw.y);
    float v0 = __half2float(h01.x), v1 = __half2float(h01.y);
    float v2 = __half2float(h23.x), v3 = __half2float(h23.y);

    float mean = wredsum(v0 + v1 + v2 + v3) * (1.f / HD);
    float d0 = v0 - mean, d1 = v1 - mean, d2 = v2 - mean, d3 = v3 - mean;
    float var = wredsum(d0*d0 + d1*d1 + d2*d2 + d3*d3) * (1.f / HD);
    float rs = rsqrtf(var + EPS);

    float n0 = d0 * rs * w[0] + b[0];
    float n1 = d1 * rs * w[1] + b[1];
    float n2 = d2 * rs * w[2] + b[2];
    float n3 = d3 * rs * w[3] + b[3];

    const float* fc = fcos + (long long)s * (HD / 2) + lane * 2;
    const float* fs = fsin + (long long)s * (HD / 2) + lane * 2;
    float c0 = fc[0], s0 = fs[0], c1 = fc[1], s1 = fs[1];

    uint2 o;
    o.x = h2u(n0 * c0 - n1 * s0, n0 * s0 + n1 * c0);
    o.y = h2u(n2 * c1 - n3 * s1, n2 * s1 + n3 * c1);
    *reinterpret_cast<uint2*>(p) = o;
}

// ---------------- launcher ----------------
extern "C" void kernel_launch(void* const* d_in, const int* in_sizes, int n_in,
                              void* d_out, int out_size)
{
    const float* x           = (const float*)d_in[0];
    const float* fcos        = (const float*)d_in[1];
    const float* fsin        = (const float*)d_in[2];
    const float* wqkv        = (const float*)d_in[4];
    const float* wo          = (const float*)d_in[5];
    const float* qn_w        = (const float*)d_in[6];
    const float* qn_b        = (const float*)d_in[7];
    const float* kn_w        = (const float*)d_in[8];
    const float* kn_b        = (const float*)d_in[9];
    const float* attn_norm_w = (const float*)d_in[10];
    const float* ffn_norm_w  = (const float*)d_in[11];
    const float* w13         = (const float*)d_in[12];
    const float* w2          = (const float*)d_in[13];
    float* out = (float*)d_out;

    __half *h16, *qkv16, *o16, *gate16, *vt16;
    __half *wqkv16, *wo16, *w13_16, *w2_16;
    float *h2;
    cudaGetSymbolAddress((void**)&h16,     g_h16);
    cudaGetSymbolAddress((void**)&qkv16,   g_qkv16);
    cudaGetSymbolAddress((void**)&o16,     g_o16);
    cudaGetSymbolAddress((void**)&gate16,  g_gate16);
    cudaGetSymbolAddress((void**)&vt16,    g_vt16);
    cudaGetSymbolAddress((void**)&wqkv16,  g_wqkv16);
    cudaGetSymbolAddress((void**)&wo16,    g_wo16);
    cudaGetSymbolAddress((void**)&w13_16,  g_w13_16);
    cudaGetSymbolAddress((void**)&w2_16,   g_w2_16);
    cudaGetSymbolAddress((void**)&h2,      g_h2);

    const int SMEM = NSTAGE * STAGE_B + 1024;
    const int FSMEM = 5 * 32768 + 256;
    cudaFuncSetAttribute((gemm_cp<float, false>),  cudaFuncAttributeMaxDynamicSharedMemorySize, SMEM);
    cudaFuncSetAttribute((gemm_cp<__half, false>), cudaFuncAttributeMaxDynamicSharedMemorySize, SMEM);
    cudaFuncSetAttribute((gemm_cp<__half, true>),  cudaFuncAttributeMaxDynamicSharedMemorySize, SMEM);
    cudaFuncSetAttribute(flash_attn, cudaFuncAttributeMaxDynamicSharedMemorySize, FSMEM);

    // 0) weights -> fp16 (w13 interleaved for fused swiglu)
    f2h_kernel<<<(QKV_DIM * (long long)DIM) / (256 * 16), 256>>>(wqkv, wqkv16, (long long)QKV_DIM * DIM);
    f2h_kernel<<<((long long)DIM * DIM) / (256 * 16), 256>>>(wo, wo16, (long long)DIM * DIM);
    f2h_w13<<<((long long)HID * DIM) / (256 * 8), 256>>>(w13, w13_16);
    f2h_kernel<<<((long long)DIM * HID) / (256 * 16), 256>>>(w2, w2_16, (long long)DIM * HID);

    // 1) h16 = rmsnorm(x)
    rmsnorm_h<<<S / 8, 256>>>(x, attn_norm_w, h16);

    // 2) qkv16 = h16 @ wqkv^T
    gemm_cp<__half, false><<<dim3(S / BM, QKV_DIM / BN, 1), 128, SMEM>>>(
        h16, wqkv16, qkv16, DIM, DIM, DIM, QKV_DIM, nullptr);

    // 3) q/k layernorm + rope (warp-per-head)
    qknorm_rope_h<<<dim3(S, 3), 256>>>(qkv16, qn_w, qn_b, kn_w, kn_b, fcos, fsin);

    // 4) vt16 = V^T
    transpose_v<<<dim3(S / 32, (NKV * HD) / 32), dim3(32, 8)>>>(qkv16, vt16);

    // 5) flash attention -> o16
    flash_attn<<<dim3(16, 16), 256, FSMEM>>>(qkv16, vt16, o16);

    // 6) h2 = x + o @ wo^T
    gemm_cp<float, false><<<dim3(S / BM, DIM / BN, 1), 128, SMEM>>>(
        o16, wo16, h2, DIM, DIM, DIM, DIM, x);

    // 7) h16 = rmsnorm(h2)
    rmsnorm_h<<<S / 8, 256>>>(h2, ffn_norm_w, h16);

    // 8) gate16 = swiglu(h16 @ w13i^T)  (fused epilogue; output N = HID pairs)
    gemm_cp<__half, true><<<dim3(S / BM, (2 * HID) / BN, 1), 128, SMEM>>>(
        h16, w13_16, gate16, DIM, DIM, DIM, HID, nullptr);

    // 9) out = h2 + gate @ w2^T
    gemm_cp<float, false><<<dim3(S / BM, DIM / BN, 1), 128, SMEM>>>(
        gate16, w2_16, out, HID, HID, HID, DIM, h2);
}

// round 10
// speedup vs baseline: 9.8745x; 1.0188x over previous
#include <cuda_runtime.h>
#include <cuda_fp16.h>
#include <math.h>
#include <stdint.h>

#define S 2048
#define DIM 2048
#define NH 16
#define NKV 8
#define HD 128
#define HID 5632
#define QKV_DIM ((NH + 2*NKV) * HD)   // 4096
#define VOFF ((NH + NKV) * HD)        // 3072
#define EPS 1e-5f

// ---------------- scratch ----------------
__device__ __align__(256) __half g_h16[(size_t)S * DIM];
__device__ __align__(256) __half g_qkv16[(size_t)S * QKV_DIM];
__device__ __align__(256) __half g_o16[(size_t)S * DIM];
__device__ __align__(256) __half g_gate16[(size_t)S * HID];
__device__ __align__(256) __half g_vt16[(size_t)NKV * HD * S];
__device__ __align__(256) __half g_wqkv16[(size_t)QKV_DIM * DIM];
__device__ __align__(256) __half g_wo16[(size_t)DIM * DIM];
__device__ __align__(256) __half g_w13_16[(size_t)2 * HID * DIM];  // interleaved (w1_j,w3_j)
__device__ __align__(256) __half g_w2_16[(size_t)DIM * HID];
__device__ float g_h2[(size_t)S * DIM];

// ---------------- helpers ----------------
__device__ __forceinline__ uint32_t sm2u(const void* p) {
    uint32_t a;
    asm("{ .reg .u64 t; cvta.to.shared.u64 t, %1; cvt.u32.u64 %0, t; }" : "=r"(a) : "l"(p));
    return a;
}

__device__ __forceinline__ uint32_t smoff(uint32_t m, uint32_t k) {
    return (m >> 1) * 128u
         + (((((m & 1u) << 2) | (k >> 3)) ^ ((m >> 1) & 7u)) << 4)
         + (k & 7u) * 2u;
}
__device__ __forceinline__ uint32_t smoff256(uint32_t r, uint32_t chunk) {
    return r * 256u + (((chunk ^ (r & 7u)) & 15u) << 4);
}

__device__ __forceinline__ uint4 ldm4(uint32_t addr) {
    uint4 r;
    asm volatile("ldmatrix.sync.aligned.m8n8.x4.shared.b16 {%0,%1,%2,%3}, [%4];"
                 : "=r"(r.x), "=r"(r.y), "=r"(r.z), "=r"(r.w) : "r"(addr));
    return r;
}

__device__ __forceinline__ void mma_f16(float* c, const uint4& a, uint32_t b0, uint32_t b1) {
    asm volatile(
        "mma.sync.aligned.m16n8k16.row.col.f32.f16.f16.f32 "
        "{%0,%1,%2,%3}, {%4,%5,%6,%7}, {%8,%9}, {%0,%1,%2,%3};"
        : "+f"(c[0]), "+f"(c[1]), "+f"(c[2]), "+f"(c[3])
        : "r"(a.x), "r"(a.y), "r"(a.z), "r"(a.w), "r"(b0), "r"(b1));
}

__device__ __forceinline__ void cpasync16(uint32_t dst, const void* src) {
    asm volatile("cp.async.cg.shared.global [%0], [%1], 16;" :: "r"(dst), "l"(src) : "memory");
}
__device__ __forceinline__ void cpcommit() {
    asm volatile("cp.async.commit_group;" ::: "memory");
}
template<int N> __device__ __forceinline__ void cpwait() {
    asm volatile("cp.async.wait_group %0;" :: "n"(N) : "memory");
}

__device__ __forceinline__ uint32_t h2u(float a, float b) {
    __half2 h = __floats2half2_rn(a, b);
    return *reinterpret_cast<uint32_t*>(&h);
}
__device__ __forceinline__ void st2(float* p, float a, float b) {
    *reinterpret_cast<float2*>(p) = make_float2(a, b);
}
__device__ __forceinline__ void st2(__half* p, float a, float b) {
    *reinterpret_cast<__half2*>(p) = __floats2half2_rn(a, b);
}
__device__ __forceinline__ float wredsum(float v) {
    #pragma unroll
    for (int o = 16; o; o >>= 1) v += __shfl_xor_sync(0xffffffffu, v, o);
    return v;
}

// ---------------- fp16 cp.async NT GEMM (2x2 warps, 64x64 warp tiles) ----------------
#define BM 128
#define BN 128
#define BK 32
#define ATILE_B 8192
#define STAGE_B 16384
#define NSTAGE 4

template<typename OutT, bool SWIGLU>
__global__ void __launch_bounds__(128, 2)
gemm_cp(const __half* __restrict__ A, const __half* __restrict__ B, OutT* __restrict__ C,
        int K, int lda, int ldb, int ldc, const float* __restrict__ res)
{
    int bm = blockIdx.x * BM;
    int bn = blockIdx.y * BN;

    extern __shared__ unsigned char smraw[];
    uint32_t smB = (sm2u(smraw) + 1023) & ~1023u;

    int tid  = threadIdx.x;
    int lane = tid & 31;
    int warp = tid >> 5;
    int wm = warp >> 1;
    int wn = warp & 1;

    int nCh = K / BK;

    int pr  = tid >> 2;
    int kc0 = (tid & 3) * 8;
    const __half* Ag = A + (long long)bm * lda;
    const __half* Bg = B + (long long)bn * ldb;
    uint32_t so[4];
    #pragma unroll
    for (int q = 0; q < 4; ++q) so[q] = smoff(pr + 32 * q, kc0);

    auto issue = [&](int c) {
        uint32_t aB = smB + (c & (NSTAGE - 1)) * STAGE_B;
        uint32_t bB = aB + ATILE_B;
        int k0 = c * BK + kc0;
        #pragma unroll
        for (int q = 0; q < 4; ++q)
            cpasync16(aB + so[q], Ag + (long long)(pr + 32 * q) * lda + k0);
        #pragma unroll
        for (int q = 0; q < 4; ++q)
            cpasync16(bB + so[q], Bg + (long long)(pr + 32 * q) * ldb + k0);
        cpcommit();
    };

    uint32_t aAdr[4], bAdr[4];
    {
        int mi = lane >> 3;
        int ra = (lane & 7) + (mi & 1) * 8;
        int ka = (mi >> 1) * 8;
        #pragma unroll
        for (int g = 0; g < 4; ++g) aAdr[g] = smoff(wm * 64 + g * 16 + ra, ka);
        int rb = (lane & 7) + (mi >> 1) * 8;
        int kb = (mi & 1) * 8;
        #pragma unroll
        for (int g = 0; g < 4; ++g) bAdr[g] = smoff(wn * 64 + g * 16 + rb, kb);
    }

    float acc[4][8][4];
    #pragma unroll
    for (int a = 0; a < 4; ++a)
        #pragma unroll
        for (int b = 0; b < 8; ++b)
            #pragma unroll
            for (int c = 0; c < 4; ++c) acc[a][b][c] = 0.f;

    #pragma unroll
    for (int c = 0; c < 3; ++c) {
        if (c < nCh) issue(c);
        else cpcommit();
    }

    for (int it = 0; it < nCh; ++it) {
        cpwait<2>();
        __syncthreads();
        if (it + 3 < nCh) issue(it + 3);
        else cpcommit();

        uint32_t aB = smB + (it & (NSTAGE - 1)) * STAGE_B;
        uint32_t bB = aB + ATILE_B;

        #pragma unroll
        for (int ks = 0; ks < 2; ++ks) {
            uint32_t kx = ks ? 32u : 0u;
            uint4 av[4], bv[4];
            #pragma unroll
            for (int g = 0; g < 4; ++g) av[g] = ldm4(aB + (aAdr[g] ^ kx));
            #pragma unroll
            for (int g = 0; g < 4; ++g) bv[g] = ldm4(bB + (bAdr[g] ^ kx));
            #pragma unroll
            for (int mi = 0; mi < 4; ++mi) {
                #pragma unroll
                for (int nj = 0; nj < 8; ++nj) {
                    uint32_t b0 = (nj & 1) ? bv[nj >> 1].z : bv[nj >> 1].x;
                    uint32_t b1 = (nj & 1) ? bv[nj >> 1].w : bv[nj >> 1].y;
                    mma_f16(acc[mi][nj], av[mi], b0, b1);
                }
            }
        }
    }
    cpwait<0>();

    int grp = lane >> 2;
    int tg  = lane & 3;
    #pragma unroll
    for (int mi = 0; mi < 4; ++mi) {
        long long r0 = bm + wm * 64 + mi * 16 + grp;
        #pragma unroll
        for (int nj = 0; nj < 8; ++nj) {
            int cl = wn * 64 + nj * 8 + tg * 2;
            if (SWIGLU) {
                int p = (bn + cl) >> 1;
                float a0 = acc[mi][nj][0], b0v = acc[mi][nj][1];
                float a1 = acc[mi][nj][2], b1v = acc[mi][nj][3];
                float g0 = a0 * b0v / (1.f + expf(-a0));
                float g1 = a1 * b1v / (1.f + expf(-a1));
                __half* Ch = (__half*)C;
                Ch[r0 * ldc + p]       = __float2half_rn(g0);
                Ch[(r0 + 8) * ldc + p] = __float2half_rn(g1);
            } else {
                int c0 = bn + cl;
                float v0 = acc[mi][nj][0], v1 = acc[mi][nj][1];
                float v2 = acc[mi][nj][2], v3 = acc[mi][nj][3];
                if (res) {
                    float2 r01 = *reinterpret_cast<const float2*>(&res[r0 * ldc + c0]);
                    float2 r23 = *reinterpret_cast<const float2*>(&res[(r0 + 8) * ldc + c0]);
                    v0 += r01.x; v1 += r01.y; v2 += r23.x; v3 += r23.y;
                }
                st2(&C[r0 * ldc + c0],       v0, v1);
                st2(&C[(r0 + 8) * ldc + c0], v2, v3);
            }
        }
    }
}

// ---------------- fused flash attention ----------------
__global__ void __launch_bounds__(256)
flash_attn(const __half* __restrict__ qkv, const __half* __restrict__ vt,
           __half* __restrict__ o)
{
    int qb = 15 - blockIdx.x;
    int h  = blockIdx.y;
    int nb = qb + 1;

    extern __shared__ unsigned char smraw[];
    uint32_t smQ = (sm2u(smraw) + 255) & ~255u;
    uint32_t smK = smQ + 32768;
    uint32_t smV = smK + 2 * 32768;

    int tid  = threadIdx.x;
    int lane = tid & 31;
    int warp = tid >> 5;
    int wrow = warp * 16;
    int grp  = lane >> 2;
    int tg   = lane & 3;

    const __half* Qg = qkv + (size_t)(qb * 128) * QKV_DIM + h * HD;
    const __half* Kg = qkv + NH * HD + (h >> 1) * HD;
    const __half* Vg = vt + (size_t)((h >> 1) * HD) * S;

    int prow = tid >> 1;
    int pc0  = (tid & 1) * 8;

    auto issueQ = [&]() {
        #pragma unroll
        for (int i = 0; i < 8; ++i) {
            int ch = pc0 + i;
            cpasync16(smQ + smoff256(prow, ch), Qg + (size_t)prow * QKV_DIM + ch * 8);
        }
    };
    auto issueKV = [&](int b) {
        uint32_t kB = smK + (b & 1) * 32768;
        uint32_t vB = smV + (b & 1) * 32768;
        #pragma unroll
        for (int i = 0; i < 8; ++i) {
            int ch = pc0 + i;
            uint32_t off = smoff256(prow, ch);
            cpasync16(kB + off, Kg + (size_t)(b * 128 + prow) * QKV_DIM + ch * 8);
            cpasync16(vB + off, Vg + (size_t)prow * S + b * 128 + ch * 8);
        }
    };

    issueQ();
    issueKV(0);
    cpcommit();

    int mi   = lane >> 3;
    int frow = (lane & 7) + (mi & 1) * 8;
    int fkc  = (mi >> 1);
    int brow = (lane & 7) + (mi >> 1) * 8;
    int bkc  = (mi & 1);

    float m0 = -1e30f, m1 = -1e30f, l0 = 0.f, l1 = 0.f;
    float O[16][4];
    #pragma unroll
    for (int j = 0; j < 16; ++j)
        #pragma unroll
        for (int c = 0; c < 4; ++c) O[j][c] = 0.f;

    uint4 qf[8];
    const float CS = 0.1275447941f;   // (1/sqrt(128)) * log2(e)

    for (int b = 0; b < nb; ++b) {
        cpwait<0>();
        __syncthreads();

        if (b == 0) {
            #pragma unroll
            for (int ks = 0; ks < 8; ++ks)
                qf[ks] = ldm4(smQ + smoff256(wrow + frow, ks * 2 + fkc));
        }
        if (b + 1 < nb) { issueKV(b + 1); cpcommit(); }

        uint32_t kB = smK + (b & 1) * 32768;
        uint32_t vB = smV + (b & 1) * 32768;

        float Sv[16][4];
        #pragma unroll
        for (int j = 0; j < 16; ++j)
            #pragma unroll
            for (int c = 0; c < 4; ++c) Sv[j][c] = 0.f;

        #pragma unroll
        for (int ks = 0; ks < 8; ++ks) {
            #pragma unroll
            for (int g = 0; g < 8; ++g) {
                uint4 bv = ldm4(kB + smoff256(g * 16 + brow, ks * 2 + bkc));
                mma_f16(Sv[2 * g],     qf[ks], bv.x, bv.y);
                mma_f16(Sv[2 * g + 1], qf[ks], bv.z, bv.w);
            }
        }

        if (b == qb) {
            int r0 = wrow + grp;
            #pragma unroll
            for (int j = 0; j < 16; ++j) {
                int c0 = j * 8 + tg * 2;
                if (c0     > r0)     Sv[j][0] = -1e30f;
                if (c0 + 1 > r0)     Sv[j][1] = -1e30f;
                if (c0     > r0 + 8) Sv[j][2] = -1e30f;
                if (c0 + 1 > r0 + 8) Sv[j][3] = -1e30f;
            }
        }

        float bm0 = -1e30f, bm1 = -1e30f;
        #pragma unroll
        for (int j = 0; j < 16; ++j) {
            bm0 = fmaxf(bm0, fmaxf(Sv[j][0], Sv[j][1]));
            bm1 = fmaxf(bm1, fmaxf(Sv[j][2], Sv[j][3]));
        }
        bm0 = fmaxf(bm0, __shfl_xor_sync(0xffffffffu, bm0, 1));
        bm0 = fmaxf(bm0, __shfl_xor_sync(0xffffffffu, bm0, 2));
        bm1 = fmaxf(bm1, __shfl_xor_sync(0xffffffffu, bm1, 1));
        bm1 = fmaxf(bm1, __shfl_xor_sync(0xffffffffu, bm1, 2));

        float nm0 = fmaxf(m0, bm0), nm1 = fmaxf(m1, bm1);
        float sc0 = exp2f((m0 - nm0) * CS), sc1 = exp2f((m1 - nm1) * CS);
        m0 = nm0; m1 = nm1;

        float rs0 = 0.f, rs1 = 0.f;
        #pragma unroll
        for (int j = 0; j < 16; ++j) {
            Sv[j][0] = exp2f((Sv[j][0] - nm0) * CS); rs0 += Sv[j][0];
            Sv[j][1] = exp2f((Sv[j][1] - nm0) * CS); rs0 += Sv[j][1];
            Sv[j][2] = exp2f((Sv[j][2] - nm1) * CS); rs1 += Sv[j][2];
            Sv[j][3] = exp2f((Sv[j][3] - nm1) * CS); rs1 += Sv[j][3];
        }
        l0 = l0 * sc0 + rs0;
        l1 = l1 * sc1 + rs1;

        #pragma unroll
        for (int j = 0; j < 16; ++j) {
            O[j][0] *= sc0; O[j][1] *= sc0;
            O[j][2] *= sc1; O[j][3] *= sc1;
        }

        #pragma unroll
        for (int ks = 0; ks < 8; ++ks) {
            uint4 pa;
            pa.x = h2u(Sv[2 * ks][0],     Sv[2 * ks][1]);
            pa.y = h2u(Sv[2 * ks][2],     Sv[2 * ks][3]);
            pa.z = h2u(Sv[2 * ks + 1][0], Sv[2 * ks + 1][1]);
            pa.w = h2u(Sv[2 * ks + 1][2], Sv[2 * ks + 1][3]);
            #pragma unroll
            for (int g = 0; g < 8; ++g) {
                uint4 bv = ldm4(vB + smoff256(g * 16 + brow, ks * 2 + bkc));
                mma_f16(O[2 * g],     pa, bv.x, bv.y);
                mma_f16(O[2 * g + 1], pa, bv.z, bv.w);
            }
        }
    }

    l0 += __shfl_xor_sync(0xffffffffu, l0, 1);
    l0 += __shfl_xor_sync(0xffffffffu, l0, 2);
    l1 += __shfl_xor_sync(0xffffffffu, l1, 1);
    l1 += __shfl_xor_sync(0xffffffffu, l1, 2);
    float inv0 = 1.f / l0, inv1 = 1.f / l1;

    __half* o0 = o + (size_t)(qb * 128 + wrow + grp) * DIM + h * HD;
    __half* o1 = o0 + 8 * DIM;
    #pragma unroll
    for (int j = 0; j < 16; ++j) {
        int c0 = j * 8 + tg * 2;
        st2(o0 + c0, O[j][0] * inv0, O[j][1] * inv0);
        st2(o1 + c0, O[j][2] * inv1, O[j][3] * inv1);
    }
}

// ---------------- fp32 -> fp16, ILP 4 ----------------
__global__ void f2h_kernel(const float* __restrict__ in, __half* __restrict__ out, long long n)
{
    long long i = ((long long)blockIdx.x * 256 + threadIdx.x) * 16;
    if (i >= n) return;
    float4 v[4];
    #pragma unroll
    for (int q = 0; q < 4; ++q)
        v[q] = *reinterpret_cast<const float4*>(in + i + q * 4);
    #pragma unroll
    for (int q = 0; q < 2; ++q) {
        uint4 o;
        o.x = h2u(v[2*q].x,   v[2*q].y);
        o.y = h2u(v[2*q].z,   v[2*q].w);
        o.z = h2u(v[2*q+1].x, v[2*q+1].y);
        o.w = h2u(v[2*q+1].z, v[2*q+1].w);
        *reinterpret_cast<uint4*>(out + i + q * 8) = o;
    }
}

// w13 interleave: out row 2j = w1 row j, row 2j+1 = w3 row j
__global__ void f2h_w13(const float* __restrict__ in, __half* __restrict__ out)
{
    long long g = ((long long)blockIdx.x * 256 + threadIdx.x) * 8;
    if (g >= (long long)HID * DIM) return;
    long long j = g / DIM;
    long long c = g - j * DIM;
    #pragma unroll
    for (int s = 0; s < 2; ++s) {
        const float* src = in + ((s ? HID : 0) + j) * (long long)DIM + c;
        float4 a = *reinterpret_cast<const float4*>(src);
        float4 b = *reinterpret_cast<const float4*>(src + 4);
        uint4 o;
        o.x = h2u(a.x, a.y); o.y = h2u(a.z, a.w);
        o.z = h2u(b.x, b.y); o.w = h2u(b.z, b.w);
        *reinterpret_cast<uint4*>(out + (2 * j + s) * (long long)DIM + c) = o;
    }
}

// ---------------- V transpose ----------------
__global__ void transpose_v(const __half* __restrict__ qkv, __half* __restrict__ vt)
{
    __shared__ float t[32][33];
    int s0 = blockIdx.x * 32;
    int d0 = blockIdx.y * 32;
    int tx = threadIdx.x, ty = threadIdx.y;
    #pragma unroll
    for (int j = 0; j < 32; j += 8)
        t[ty + j][tx] = __half2float(qkv[(long long)(s0 + ty + j) * QKV_DIM + VOFF + d0 + tx]);
    __syncthreads();
    #pragma unroll
    for (int j = 0; j < 32; j += 8)
        vt[(long long)(d0 + ty + j) * S + s0 + tx] = __float2half_rn(t[tx][ty + j]);
}

// ---------------- warp-per-row rmsnorm ----------------
__global__ void rmsnorm_h(const float* __restrict__ x, const float* __restrict__ w,
                          __half* __restrict__ out)
{
    int row  = blockIdx.x * 8 + (threadIdx.x >> 5);
    int lane = threadIdx.x & 31;
    const float* xr = x + (long long)row * DIM;

    float s = 0.f;
    float4 v[16];
    #pragma unroll
    for (int i = 0; i < 16; ++i) {
        v[i] = *reinterpret_cast<const float4*>(xr + lane * 4 + i * 128);
        s += v[i].x * v[i].x + v[i].y * v[i].y + v[i].z * v[i].z + v[i].w * v[i].w;
    }
    s = wredsum(s);
    float inv = rsqrtf(s / (float)DIM + EPS);

    __half* orow = out + (long long)row * DIM;
    #pragma unroll
    for (int i = 0; i < 16; ++i) {
        int c = lane * 4 + i * 128;
        uint2 o;
        o.x = h2u(v[i].x * inv * w[c],     v[i].y * inv * w[c + 1]);
        o.y = h2u(v[i].z * inv * w[c + 2], v[i].w * inv * w[c + 3]);
        *reinterpret_cast<uint2*>(orow + c) = o;
    }
}

// ---------------- warp-per-head layernorm + rope ----------------
__global__ void qknorm_rope_h(__half* __restrict__ qkv,
                              const float* __restrict__ qn_w, const float* __restrict__ qn_b,
                              const float* __restrict__ kn_w, const float* __restrict__ kn_b,
                              const float* __restrict__ fcos, const float* __restrict__ fsin)
{
    int s    = blockIdx.x;
    int hh   = blockIdx.y * 8 + (threadIdx.x >> 5);
    int lane = threadIdx.x & 31;
    bool isq = (hh < NH);
    int col  = isq ? hh * HD : NH * HD + (hh - NH) * HD;
    __half* p = qkv + (long long)s * QKV_DIM + col + lane * 4;
    const float* w = (isq ? qn_w : kn_w) + lane * 4;
    const float* b = (isq ? qn_b : kn_b) + lane * 4;

    uint2 raw = *reinterpret_cast<const uint2*>(p);
    __half2 h01 = *reinterpret_cast<__half2*>(&raw.x);
    __half2 h23 = *reinterpret_cast<__half2*>(&raw.y);
    float v0 = __half2float(h01.x), v1 = __half2float(h01.y);
    float v2 = __half2float(h23.x), v3 = __half2float(h23.y);

    float mean = wredsum(v0 + v1 + v2 + v3) * (1.f / HD);
    float d0 = v0 - mean, d1 = v1 - mean, d2 = v2 - mean, d3 = v3 - mean;
    float var = wredsum(d0*d0 + d1*d1 + d2*d2 + d3*d3) * (1.f / HD);
    float rs = rsqrtf(var + EPS);

    float n0 = d0 * rs * w[0] + b[0];
    float n1 = d1 * rs * w[1] + b[1];
    float n2 = d2 * rs * w[2] + b[2];
    float n3 = d3 * rs * w[3] + b[3];

    const float* fc = fcos + (long long)s * (HD / 2) + lane * 2;
    const float* fs = fsin + (long long)s * (HD / 2) + lane * 2;
    float c0 = fc[0], s0 = fs[0], c1 = fc[1], s1 = fs[1];

    uint2 o;
    o.x = h2u(n0 * c0 - n1 * s0, n0 * s0 + n1 * c0);
    o.y = h2u(n2 * c1 - n3 * s1, n2 * s1 + n3 * c1);
    *reinterpret_cast<uint2*>(p) = o;
}

// ---------------- launcher ----------------
extern "C" void kernel_launch(void* const* d_in, const int* in_sizes, int n_in,
                              void* d_out, int out_size)
{
    const float* x           = (const float*)d_in[0];
    const float* fcos        = (const float*)d_in[1];
    const float* fsin        = (const float*)d_in[2];
    const float* wqkv        = (const float*)d_in[4];
    const float* wo          = (const float*)d_in[5];
    const float* qn_w        = (const float*)d_in[6];
    const float* qn_b        = (const float*)d_in[7];
    const float* kn_w        = (const float*)d_in[8];
    const float* kn_b        = (const float*)d_in[9];
    const float* attn_norm_w = (const float*)d_in[10];
    const float* ffn_norm_w  = (const float*)d_in[11];
    const float* w13         = (const float*)d_in[12];
    const float* w2          = (const float*)d_in[13];
    float* out = (float*)d_out;

    __half *h16, *qkv16, *o16, *gate16, *vt16;
    __half *wqkv16, *wo16, *w13_16, *w2_16;
    float *h2;
    cudaGetSymbolAddress((void**)&h16,     g_h16);
    cudaGetSymbolAddress((void**)&qkv16,   g_qkv16);
    cudaGetSymbolAddress((void**)&o16,     g_o16);
    cudaGetSymbolAddress((void**)&gate16,  g_gate16);
    cudaGetSymbolAddress((void**)&vt16,    g_vt16);
    cudaGetSymbolAddress((void**)&wqkv16,  g_wqkv16);
    cudaGetSymbolAddress((void**)&wo16,    g_wo16);
    cudaGetSymbolAddress((void**)&w13_16,  g_w13_16);
    cudaGetSymbolAddress((void**)&w2_16,   g_w2_16);
    cudaGetSymbolAddress((void**)&h2,      g_h2);

    // side streams + events: created once (host-side objects, no device mem)
    static cudaStream_t sW = nullptr, sT = nullptr;
    static cudaEvent_t evRoot = nullptr, evW = nullptr, evQ = nullptr, evT = nullptr;
    if (!sW) {
        cudaStreamCreateWithFlags(&sW, cudaStreamNonBlocking);
        cudaStreamCreateWithFlags(&sT, cudaStreamNonBlocking);
        cudaEventCreateWithFlags(&evRoot, cudaEventDisableTiming);
        cudaEventCreateWithFlags(&evW,    cudaEventDisableTiming);
        cudaEventCreateWithFlags(&evQ,    cudaEventDisableTiming);
        cudaEventCreateWithFlags(&evT,    cudaEventDisableTiming);
    }

    const int SMEM = NSTAGE * STAGE_B + 1024;
    const int FSMEM = 5 * 32768 + 256;
    cudaFuncSetAttribute((gemm_cp<float, false>),  cudaFuncAttributeMaxDynamicSharedMemorySize, SMEM);
    cudaFuncSetAttribute((gemm_cp<__half, false>), cudaFuncAttributeMaxDynamicSharedMemorySize, SMEM);
    cudaFuncSetAttribute((gemm_cp<__half, true>),  cudaFuncAttributeMaxDynamicSharedMemorySize, SMEM);
    cudaFuncSetAttribute(flash_attn, cudaFuncAttributeMaxDynamicSharedMemorySize, FSMEM);

    // ---- fork: stream sW converts wo/w13/w2 while main stream runs qkv path ----
    cudaEventRecord(evRoot, 0);
    cudaStreamWaitEvent(sW, evRoot, 0);
    f2h_kernel<<<((long long)DIM * DIM) / (256 * 16), 256, 0, sW>>>(wo, wo16, (long long)DIM * DIM);
    f2h_w13<<<((long long)HID * DIM) / (256 * 8), 256, 0, sW>>>(w13, w13_16);
    f2h_kernel<<<((long long)DIM * HID) / (256 * 16), 256, 0, sW>>>(w2, w2_16, (long long)DIM * HID);
    cudaEventRecord(evW, sW);

    // main stream: wqkv conversion + attn-norm (both needed for qkv GEMM)
    f2h_kernel<<<(QKV_DIM * (long long)DIM) / (256 * 16), 256>>>(wqkv, wqkv16, (long long)QKV_DIM * DIM);
    rmsnorm_h<<<S / 8, 256>>>(x, attn_norm_w, h16);

    // qkv GEMM
    gemm_cp<__half, false><<<dim3(S / BM, QKV_DIM / BN, 1), 128, SMEM>>>(
        h16, wqkv16, qkv16, DIM, DIM, DIM, QKV_DIM, nullptr);

    // fork: transpose_v (V columns) in parallel with qknorm (Q/K columns)
    cudaEventRecord(evQ, 0);
    cudaStreamWaitEvent(sT, evQ, 0);
    transpose_v<<<dim3(S / 32, (NKV * HD) / 32), dim3(32, 8), 0, sT>>>(qkv16, vt16);
    cudaEventRecord(evT, sT);

    qknorm_rope_h<<<dim3(S, 3), 256>>>(qkv16, qn_w, qn_b, kn_w, kn_b, fcos, fsin);
    cudaStreamWaitEvent(0, evT, 0);

    // flash attention -> o16
    flash_attn<<<dim3(16, 16), 256, FSMEM>>>(qkv16, vt16, o16);

    // join weight-conversion branch before WO GEMM
    cudaStreamWaitEvent(0, evW, 0);

    // h2 = x + o @ wo^T
    gemm_cp<float, false><<<dim3(S / BM, DIM / BN, 1), 128, SMEM>>>(
        o16, wo16, h2, DIM, DIM, DIM, DIM, x);

    // h16 = rmsnorm(h2)
    rmsnorm_h<<<S / 8, 256>>>(h2, ffn_norm_w, h16);

    // gate16 = swiglu(h16 @ w13i^T)
    gemm_cp<__half, true><<<dim3(S / BM, (2 * HID) / BN, 1), 128, SMEM>>>(
        h16, w13_16, gate16, DIM, DIM, DIM, HID, nullptr);

    // out = h2 + gate @ w2^T
    gemm_cp<float, false><<<dim3(S / BM, DIM / BN, 1), 128, SMEM>>>(
        gate16, w2_16, out, HID, HID, HID, DIM, h2);
}